// round 2
// baseline (speedup 1.0000x reference)
#include <cuda_runtime.h>
#include <math.h>

#define HN 512
#define NS 64
#define LLEN 2048
#define CHUNKS 32

// ---------------- device scratch (no dynamic allocation) ----------------
__device__ float2 g_m[HN][NS];
__device__ float2 g_v[HN][NS];
__device__ float2 g_r[HN][NS];
__device__ float2 g_bb[HN][NS];
__device__ float2 g_cct[HN][NS];
__device__ float2 g_cb[HN][NS];
__device__ float  g_taps[HN][NS];
__device__ float2 g_T0[HN][NS * NS];
__device__ float2 g_T1[HN][NS * NS];
__device__ float2 g_AB64[HN][NS * NS];
__device__ float2 g_K[HN][NS * NS];    // [p][n]
__device__ float2 g_Wt[HN][NS * NS];   // [n][tau]
__device__ float2 g_E[HN][CHUNKS][NS];
__device__ float2 g_XS[HN][CHUNKS][NS];

// ---------------- complex helpers ----------------
__device__ __forceinline__ float2 cmul(float2 a, float2 b) {
    return make_float2(a.x * b.x - a.y * b.y, a.x * b.y + a.y * b.x);
}
__device__ __forceinline__ float2 cadd(float2 a, float2 b) { return make_float2(a.x + b.x, a.y + b.y); }
__device__ __forceinline__ float2 csub(float2 a, float2 b) { return make_float2(a.x - b.x, a.y - b.y); }
__device__ __forceinline__ float2 conj2(float2 a) { return make_float2(a.x, -a.y); }
__device__ __forceinline__ float2 crcp(float2 a) {
    float inv = 1.0f / (a.x * a.x + a.y * a.y);
    return make_float2(a.x * inv, -a.y * inv);
}

// 64-thread (2 warp) block reduction of a complex value.
__device__ __forceinline__ float2 blockReduce64(float2 val, float2* sbuf) {
    #pragma unroll
    for (int o = 16; o > 0; o >>= 1) {
        val.x += __shfl_xor_sync(0xffffffffu, val.x, o);
        val.y += __shfl_xor_sync(0xffffffffu, val.y, o);
    }
    int tid = threadIdx.x;
    if ((tid & 31) == 0) sbuf[tid >> 5] = val;
    __syncthreads();
    float2 res = make_float2(sbuf[0].x + sbuf[1].x, sbuf[0].y + sbuf[1].y);
    __syncthreads();
    return res;
}

// ---------------- kernel 1: derive params, dense Ab, K chain ----------------
__global__ void derive_kernel(const float* __restrict__ Lre, const float* __restrict__ Lim,
                              const float* __restrict__ Pre, const float* __restrict__ Pim,
                              const float* __restrict__ Bre, const float* __restrict__ Bim,
                              const float* __restrict__ Cin, const float* __restrict__ lstep) {
    int h = blockIdx.x;
    int n = threadIdx.x;
    __shared__ float2 sred[2];
    __shared__ float2 sr[NS];

    float dt = expf(lstep[h]);
    float tdt = 2.0f / dt;
    float lre = fminf(Lre[h * NS + n], -1e-4f);
    float lim = Lim[h * NS + n];

    // d = 1/(2/dt - lambda)
    float2 den = make_float2(tdt - lre, -lim);
    float2 d = crcp(den);
    float2 a0 = make_float2(tdt + lre, lim);
    float2 m = cmul(d, a0);
    float2 P = make_float2(Pre[h * NS + n], Pim[h * NS + n]);
    float p2 = P.x * P.x + P.y * P.y;

    float2 s = blockReduce64(make_float2(p2 * d.x, p2 * d.y), sred);
    float2 c = crcp(make_float2(1.0f + s.x, s.y));
    float2 v = cmul(d, P);
    float2 onem = make_float2(1.0f + m.x, m.y);
    float2 r = cmul(c, cmul(conj2(P), onem));

    float2 B = make_float2(Bre[h * NS + n], Bim[h * NS + n]);
    float2 t1 = cmul(cmul(conj2(P), B), d);
    float2 sB = blockReduce64(t1, sred);
    float2 cs = cmul(c, sB);
    float2 dB = cmul(d, B);
    float2 vcs = cmul(cs, v);
    float2 bb = make_float2(2.0f * (dB.x - vcs.x), 2.0f * (dB.y - vcs.y));

    float2 cct = make_float2(Cin[h * 2 * NS + 2 * n], -Cin[h * 2 * NS + 2 * n + 1]);

    g_m[h][n] = m; g_v[h][n] = v; g_r[h][n] = r; g_bb[h][n] = bb; g_cct[h][n] = cct;

    sr[n] = r;
    __syncthreads();
    // Dense Ab row n: Ab[n][j] = (n==j)m_n - v_n r_j
    #pragma unroll 4
    for (int j = 0; j < NS; j++) {
        float2 e = cmul(v, sr[j]);
        float2 val = make_float2(-e.x, -e.y);
        if (j == n) { val.x += m.x; val.y += m.y; }
        g_T0[h][n * NS + j] = val;
    }
    __syncthreads();

    // K chain: K_0 = Bb ; K_{p+1} = m*K_p - v*(r . K_p)
    float2 x = bb;
    g_K[h][0 * NS + n] = x;
    for (int p = 1; p < NS; p++) {
        float2 dot = blockReduce64(cmul(r, x), sred);
        x = csub(cmul(m, x), cmul(v, dot));
        g_K[h][p * NS + n] = x;
    }
}

// ---------------- kernel 2: 64x64 complex matrix squaring ----------------
__device__ __forceinline__ float2* mat_base(int id) {
    if (id == 0) return &g_T0[0][0];
    if (id == 1) return &g_T1[0][0];
    return &g_AB64[0][0];
}

__global__ __launch_bounds__(256) void sq_kernel(int sid, int did) {
    int h = blockIdx.x;
    const float2* __restrict__ S = mat_base(sid) + h * NS * NS;
    float2* __restrict__ Dm = mat_base(did) + h * NS * NS;

    __shared__ float are[NS][NS + 1];
    __shared__ float aim[NS][NS + 1];
    int t = threadIdx.x;
    for (int idx = t; idx < NS * NS; idx += 256) {
        float2 f = S[idx];
        are[idx >> 6][idx & 63] = f.x;
        aim[idx >> 6][idx & 63] = f.y;
    }
    __syncthreads();

    int r0 = (t >> 4) * 4;
    int c0 = (t & 15) * 4;
    float accre[4][4] = {}, accim[4][4] = {};
    #pragma unroll 4
    for (int k = 0; k < NS; k++) {
        float ar[4], ai[4], br[4], bi[4];
        #pragma unroll
        for (int i = 0; i < 4; i++) { ar[i] = are[r0 + i][k]; ai[i] = aim[r0 + i][k]; }
        #pragma unroll
        for (int j = 0; j < 4; j++) { br[j] = are[k][c0 + j]; bi[j] = aim[k][c0 + j]; }
        #pragma unroll
        for (int i = 0; i < 4; i++)
            #pragma unroll
            for (int j = 0; j < 4; j++) {
                accre[i][j] = fmaf(ar[i], br[j], fmaf(-ai[i], bi[j], accre[i][j]));
                accim[i][j] = fmaf(ar[i], bi[j], fmaf(ai[i], br[j], accim[i][j]));
            }
    }
    #pragma unroll
    for (int i = 0; i < 4; i++)
        #pragma unroll
        for (int j = 0; j < 4; j++)
            Dm[(r0 + i) * NS + c0 + j] = make_float2(accre[i][j], accim[i][j]);
}

// ---------------- kernel 3: Cb (Neumann), Wt chain, taps ----------------
__global__ void cbw_kernel() {
    int h = blockIdx.x;
    int n = threadIdx.x;
    __shared__ float gre[NS][NS + 1];
    __shared__ float gim[NS][NS + 1];
    __shared__ float2 sw[NS];
    __shared__ float2 sred[2];

    // G = Ab^2048 lives in T0
    for (int k = 0; k < NS; k++) {
        float2 f = g_T0[h][k * NS + n];
        gre[k][n] = f.x;
        gim[k][n] = f.y;
    }
    float2 cct = g_cct[h][n];
    float2 w = cct;
    __syncthreads();

    // w <- cct + w G   (row-vector iteration)
    for (int it = 0; it < 24; it++) {
        sw[n] = w;
        __syncthreads();
        float2 acc = cct;
        #pragma unroll 4
        for (int i = 0; i < NS; i++) {
            float2 gi = make_float2(gre[i][n], gim[i][n]);
            float2 wi = sw[i];
            acc.x = fmaf(wi.x, gi.x, fmaf(-wi.y, gi.y, acc.x));
            acc.y = fmaf(wi.x, gi.y, fmaf(wi.y, gi.x, acc.y));
        }
        __syncthreads();
        w = acc;
    }
    float2 cb = w;
    g_cb[h][n] = cb;

    // Wrow chain: wr <- m*wr - (wr . v) r ; store transposed Wt[n][tau]
    float2 m = g_m[h][n], v = g_v[h][n], r = g_r[h][n];
    float2 wr = cb;
    for (int tau = 0; tau < NS; tau++) {
        float2 dot = blockReduce64(cmul(wr, v), sred);
        wr = csub(cmul(m, wr), cmul(dot, r));
        g_Wt[h][n * NS + tau] = wr;
    }

    // taps: k_p = Re( sum_i cb_i K[p][i] ), thread n handles p = n
    sw[n] = cb;
    __syncthreads();
    float acc = 0.0f;
    for (int i = 0; i < NS; i++) {
        float2 kp = g_K[h][n * NS + i];
        float2 ci = sw[i];
        acc += ci.x * kp.x - ci.y * kp.y;
    }
    g_taps[h][n] = acc;
}

// ---------------- kernel 4: chunk-local ends E + causal conv -> out ----------------
__global__ __launch_bounds__(256) void econv_kernel(const float* __restrict__ u,
                                                    const float* __restrict__ Din,
                                                    float* __restrict__ out) {
    int h = blockIdx.x;
    int t = threadIdx.x;
    __shared__ float su[LLEN / 1];     // 2048 u values for this head: 8KB
    __shared__ float kre[NS][NS];
    __shared__ float kim[NS][NS];
    __shared__ float staps[NS];

    for (int i = t; i < LLEN; i += 256) su[i] = u[i * HN + h];
    for (int idx = t; idx < NS * NS; idx += 256) {
        float2 f = g_K[h][idx];
        kre[idx >> 6][idx & 63] = f.x;
        kim[idx >> 6][idx & 63] = f.y;
    }
    if (t < NS) staps[t] = g_taps[h][t];
    __syncthreads();

    float Dh = Din[h];
    int n = t & 63;
    int jb = t >> 6;
    for (int jj = 0; jj < 8; jj++) {
        int j = jb * 8 + jj;
        const float* uj = &su[j * 64];
        // E_j[n] = sum_s K[63-s][n] * u_loc[s]
        float er = 0.0f, ei = 0.0f;
        #pragma unroll 4
        for (int s = 0; s < 64; s++) {
            float us = uj[s];
            er = fmaf(kre[63 - s][n], us, er);
            ei = fmaf(kim[63 - s][n], us, ei);
        }
        g_E[h][j][n] = make_float2(er, ei);
        // causal conv part (tau = n)
        float yc = 0.0f;
        for (int s = 0; s <= n; s++) yc = fmaf(staps[n - s], uj[s], yc);
        int tg = j * 64 + n;
        out[tg * HN + h] = yc + Dh * su[tg];
    }
}

// ---------------- kernel 5: carry propagation with dense Ab^64 ----------------
__global__ void prop_kernel(const float* __restrict__ x0re, const float* __restrict__ x0im) {
    int h = blockIdx.x;
    int n = threadIdx.x;
    __shared__ float ar[NS][NS + 1];
    __shared__ float ai[NS][NS + 1];
    __shared__ float2 sx[NS];

    for (int k = 0; k < NS; k++) {
        float2 f = g_AB64[h][k * NS + n];
        ar[k][n] = f.x;
        ai[k][n] = f.y;
    }
    float2 x = make_float2(x0re[n * HN + h], x0im[n * HN + h]);
    __syncthreads();

    for (int j = 0; j < CHUNKS; j++) {
        g_XS[h][j][n] = x;
        sx[n] = x;
        __syncthreads();
        float2 acc = g_E[h][j][n];
        #pragma unroll 4
        for (int k = 0; k < NS; k++) {
            float2 a = make_float2(ar[n][k], ai[n][k]);
            float2 xk = sx[k];
            acc.x = fmaf(a.x, xk.x, fmaf(-a.y, xk.y, acc.x));
            acc.y = fmaf(a.x, xk.y, fmaf(a.y, xk.x, acc.y));
        }
        __syncthreads();
        x = acc;
    }
}

// ---------------- kernel 6: carry contribution Y1 -> out ----------------
__global__ __launch_bounds__(256) void y1_kernel(float* __restrict__ out) {
    int h = blockIdx.x;
    int t = threadIdx.x;
    __shared__ float wre[NS][NS];   // [n][tau]
    __shared__ float wim[NS][NS];

    for (int idx = t; idx < NS * NS; idx += 256) {
        float2 f = g_Wt[h][idx];
        wre[idx >> 6][idx & 63] = f.x;
        wim[idx >> 6][idx & 63] = f.y;
    }
    __syncthreads();

    int tau = t & 63;
    int jb = t >> 6;
    for (int jj = 0; jj < 8; jj++) {
        int j = jb * 8 + jj;
        float acc = 0.0f;
        #pragma unroll 4
        for (int n = 0; n < NS; n++) {
            float2 xs = g_XS[h][j][n];   // uniform across warp -> L1 broadcast
            acc = fmaf(wre[n][tau], xs.x, fmaf(-wim[n][tau], xs.y, acc));
        }
        int tg = j * 64 + tau;
        out[tg * HN + h] += acc;
    }
}

// ---------------- launch ----------------
extern "C" void kernel_launch(void* const* d_in, const int* in_sizes, int n_in,
                              void* d_out, int out_size) {
    const float* u     = (const float*)d_in[0];
    const float* x0re  = (const float*)d_in[1];
    const float* x0im  = (const float*)d_in[2];
    const float* Lre   = (const float*)d_in[3];
    const float* Lim   = (const float*)d_in[4];
    const float* Pre   = (const float*)d_in[5];
    const float* Pim   = (const float*)d_in[6];
    const float* Bre   = (const float*)d_in[7];
    const float* Bim   = (const float*)d_in[8];
    const float* Cin   = (const float*)d_in[9];
    const float* Din   = (const float*)d_in[10];
    const float* lstep = (const float*)d_in[11];
    float* out = (float*)d_out;

    derive_kernel<<<HN, 64>>>(Lre, Lim, Pre, Pim, Bre, Bim, Cin, lstep);

    // squarings: Ab in T0 -> ... -> Ab^64 in AB64 -> ... -> Ab^2048 in T0
    sq_kernel<<<HN, 256>>>(0, 1);  // A^2
    sq_kernel<<<HN, 256>>>(1, 0);  // A^4
    sq_kernel<<<HN, 256>>>(0, 1);  // A^8
    sq_kernel<<<HN, 256>>>(1, 0);  // A^16
    sq_kernel<<<HN, 256>>>(0, 1);  // A^32
    sq_kernel<<<HN, 256>>>(1, 2);  // A^64 -> AB64
    sq_kernel<<<HN, 256>>>(2, 0);  // A^128
    sq_kernel<<<HN, 256>>>(0, 1);  // A^256
    sq_kernel<<<HN, 256>>>(1, 0);  // A^512
    sq_kernel<<<HN, 256>>>(0, 1);  // A^1024
    sq_kernel<<<HN, 256>>>(1, 0);  // A^2048 -> T0

    cbw_kernel<<<HN, 64>>>();
    econv_kernel<<<HN, 256>>>(u, Din, out);
    prop_kernel<<<HN, 64>>>(x0re, x0im);
    y1_kernel<<<HN, 256>>>(out);
}

// round 3
// speedup vs baseline: 1.1545x; 1.1545x over previous
#include <cuda_runtime.h>
#include <math.h>

#define HN 512
#define NS 64
#define LLEN 2048
#define CHUNKS 32

// ---------------- device scratch (no dynamic allocation) ----------------
__device__ float2 g_m[HN][NS];
__device__ float2 g_v[HN][NS];
__device__ float2 g_r[HN][NS];
__device__ float2 g_bb[HN][NS];
__device__ float2 g_cct[HN][NS];
__device__ float2 g_cb[HN][NS];
__device__ float  g_taps[HN][NS];
__device__ float2 g_T0[HN][NS * NS];     // Ab, later Ab^2048
__device__ float2 g_AB64[HN][NS * NS];   // Ab^64
__device__ float2 g_K[HN][NS * NS];      // [p][n]
__device__ float2 g_Wt[HN][NS * NS];     // [n][tau]
__device__ float2 g_E[HN][CHUNKS][NS];
__device__ float2 g_XS[HN][CHUNKS][NS];

// ---------------- complex helpers ----------------
__device__ __forceinline__ float2 cmul(float2 a, float2 b) {
    return make_float2(a.x * b.x - a.y * b.y, a.x * b.y + a.y * b.x);
}
__device__ __forceinline__ float2 csub(float2 a, float2 b) { return make_float2(a.x - b.x, a.y - b.y); }
__device__ __forceinline__ float2 conj2(float2 a) { return make_float2(a.x, -a.y); }
__device__ __forceinline__ float2 crcp(float2 a) {
    float inv = 1.0f / (a.x * a.x + a.y * a.y);
    return make_float2(a.x * inv, -a.y * inv);
}

// f32x2 packed FMA: d += a * b (element-wise on 2 packed floats)
__device__ __forceinline__ void fma2(unsigned long long& d, unsigned long long a, unsigned long long b) {
    asm("fma.rn.f32x2 %0, %1, %2, %0;" : "+l"(d) : "l"(a), "l"(b));
}
__device__ __forceinline__ float2 u2f(unsigned long long u) {
    float2 f;
    asm("mov.b64 {%0, %1}, %2;" : "=f"(f.x), "=f"(f.y) : "l"(u));
    return f;
}

// 64-thread (2 warp) block reduction of a complex value.
__device__ __forceinline__ float2 blockReduce64(float2 val, float2* sbuf) {
    #pragma unroll
    for (int o = 16; o > 0; o >>= 1) {
        val.x += __shfl_xor_sync(0xffffffffu, val.x, o);
        val.y += __shfl_xor_sync(0xffffffffu, val.y, o);
    }
    int tid = threadIdx.x;
    if ((tid & 31) == 0) sbuf[tid >> 5] = val;
    __syncthreads();
    float2 res = make_float2(sbuf[0].x + sbuf[1].x, sbuf[0].y + sbuf[1].y);
    __syncthreads();
    return res;
}

// ---------------- kernel 1: derive params, dense Ab, K chain ----------------
__global__ void derive_kernel(const float* __restrict__ Lre, const float* __restrict__ Lim,
                              const float* __restrict__ Pre, const float* __restrict__ Pim,
                              const float* __restrict__ Bre, const float* __restrict__ Bim,
                              const float* __restrict__ Cin, const float* __restrict__ lstep) {
    int h = blockIdx.x;
    int n = threadIdx.x;
    __shared__ float2 sred[2];
    __shared__ float2 sr[NS];

    float dt = expf(lstep[h]);
    float tdt = 2.0f / dt;
    float lre = fminf(Lre[h * NS + n], -1e-4f);
    float lim = Lim[h * NS + n];

    float2 den = make_float2(tdt - lre, -lim);
    float2 d = crcp(den);
    float2 a0 = make_float2(tdt + lre, lim);
    float2 m = cmul(d, a0);
    float2 P = make_float2(Pre[h * NS + n], Pim[h * NS + n]);
    float p2 = P.x * P.x + P.y * P.y;

    float2 s = blockReduce64(make_float2(p2 * d.x, p2 * d.y), sred);
    float2 c = crcp(make_float2(1.0f + s.x, s.y));
    float2 v = cmul(d, P);
    float2 onem = make_float2(1.0f + m.x, m.y);
    float2 r = cmul(c, cmul(conj2(P), onem));

    float2 B = make_float2(Bre[h * NS + n], Bim[h * NS + n]);
    float2 t1 = cmul(cmul(conj2(P), B), d);
    float2 sB = blockReduce64(t1, sred);
    float2 cs = cmul(c, sB);
    float2 dB = cmul(d, B);
    float2 vcs = cmul(cs, v);
    float2 bb = make_float2(2.0f * (dB.x - vcs.x), 2.0f * (dB.y - vcs.y));

    float2 cct = make_float2(Cin[h * 2 * NS + 2 * n], -Cin[h * 2 * NS + 2 * n + 1]);

    g_m[h][n] = m; g_v[h][n] = v; g_r[h][n] = r; g_bb[h][n] = bb; g_cct[h][n] = cct;

    sr[n] = r;
    __syncthreads();
    #pragma unroll 4
    for (int j = 0; j < NS; j++) {
        float2 e = cmul(v, sr[j]);
        float2 val = make_float2(-e.x, -e.y);
        if (j == n) { val.x += m.x; val.y += m.y; }
        g_T0[h][n * NS + j] = val;
    }
    __syncthreads();

    // K chain: K_0 = Bb ; K_{p+1} = m*K_p - v*(r . K_p)
    float2 x = bb;
    g_K[h][0 * NS + n] = x;
    for (int p = 1; p < NS; p++) {
        float2 dot = blockReduce64(cmul(r, x), sred);
        x = csub(cmul(m, x), cmul(v, dot));
        g_K[h][p * NS + n] = x;
    }
}

// ---------------- kernel 2: fused 11 squarings, f32x2 packed ----------------
// smem layout (dynamic):
//   are_dup[64][66] float2  : (re,re) of A[i][k] at [k][i]
//   aim_dup[64][66] float2  : (im,im) of A[i][k] at [k][i]
//   brem[64][66] float      : re of A[k][j] at [k][j]
//   bimm[64][66] float      : im of A[k][j] at [k][j]
#define DROW 66
#define SM_BYTES (2 * 64 * DROW * 8 + 2 * 64 * DROW * 4)

__global__ __launch_bounds__(256, 2) void powers_kernel() {
    extern __shared__ char smraw[];
    float2* are_dup = (float2*)smraw;
    float2* aim_dup = are_dup + 64 * DROW;
    float*  brem    = (float*)(aim_dup + 64 * DROW);
    float*  bimm    = brem + 64 * DROW;

    int h = blockIdx.x;
    int t = threadIdx.x;

    // initial load: Ab from g_T0 into both layouts
    for (int idx = t; idx < NS * NS; idx += 256) {
        int r = idx >> 6, c = idx & 63;
        float2 f = g_T0[h][idx];
        brem[r * DROW + c] = f.x;
        bimm[r * DROW + c] = f.y;
        are_dup[c * DROW + r] = make_float2(f.x, f.x);
        aim_dup[c * DROW + r] = make_float2(f.y, f.y);
    }
    __syncthreads();

    int r0 = (t >> 4) * 4;          // 4 output rows
    int ci = t & 15;
    int j0a = 2 * ci;               // column pair A
    int j0b = 2 * ci + 32;          // column pair B

    for (int step = 0; step < 11; step++) {
        unsigned long long accRR[4][2] = {}, accII[4][2] = {}, accRI[4][2] = {}, accIR[4][2] = {};

        #pragma unroll 16
        for (int k = 0; k < NS; k++) {
            unsigned long long a_re[4], a_im[4];
            #pragma unroll
            for (int i = 0; i < 4; i++) {
                a_re[i] = *(const unsigned long long*)&are_dup[k * DROW + r0 + i];
                a_im[i] = *(const unsigned long long*)&aim_dup[k * DROW + r0 + i];
            }
            unsigned long long b_re0 = *(const unsigned long long*)&brem[k * DROW + j0a];
            unsigned long long b_re1 = *(const unsigned long long*)&brem[k * DROW + j0b];
            unsigned long long b_im0 = *(const unsigned long long*)&bimm[k * DROW + j0a];
            unsigned long long b_im1 = *(const unsigned long long*)&bimm[k * DROW + j0b];
            #pragma unroll
            for (int i = 0; i < 4; i++) {
                fma2(accRR[i][0], a_re[i], b_re0);
                fma2(accII[i][0], a_im[i], b_im0);
                fma2(accRI[i][0], a_re[i], b_im0);
                fma2(accIR[i][0], a_im[i], b_re0);
                fma2(accRR[i][1], a_re[i], b_re1);
                fma2(accII[i][1], a_im[i], b_im1);
                fma2(accRI[i][1], a_re[i], b_im1);
                fma2(accIR[i][1], a_im[i], b_re1);
            }
        }
        __syncthreads();   // all reads of the old matrix are done

        bool save64 = (step == 5);
        bool save2048 = (step == 10);
        #pragma unroll
        for (int i = 0; i < 4; i++) {
            #pragma unroll
            for (int p = 0; p < 2; p++) {
                float2 rr = u2f(accRR[i][p]);
                float2 ii = u2f(accII[i][p]);
                float2 rim = u2f(accRI[i][p]);
                float2 ir = u2f(accIR[i][p]);
                float re0 = rr.x - ii.x, re1 = rr.y - ii.y;
                float im0 = rim.x + ir.x, im1 = rim.y + ir.y;
                int r = r0 + i;
                int j = p ? j0b : j0a;
                brem[r * DROW + j] = re0;     brem[r * DROW + j + 1] = re1;
                bimm[r * DROW + j] = im0;     bimm[r * DROW + j + 1] = im1;
                are_dup[j * DROW + r] = make_float2(re0, re0);
                are_dup[(j + 1) * DROW + r] = make_float2(re1, re1);
                aim_dup[j * DROW + r] = make_float2(im0, im0);
                aim_dup[(j + 1) * DROW + r] = make_float2(im1, im1);
                if (save64) {
                    g_AB64[h][r * NS + j] = make_float2(re0, im0);
                    g_AB64[h][r * NS + j + 1] = make_float2(re1, im1);
                }
                if (save2048) {
                    g_T0[h][r * NS + j] = make_float2(re0, im0);
                    g_T0[h][r * NS + j + 1] = make_float2(re1, im1);
                }
            }
        }
        __syncthreads();
    }
}

// ---------------- kernel 3: Cb (Neumann), Wt chain, taps ----------------
__global__ void cbw_kernel() {
    int h = blockIdx.x;
    int n = threadIdx.x;
    __shared__ float gre[NS][NS + 1];
    __shared__ float gim[NS][NS + 1];
    __shared__ float2 sw[NS];
    __shared__ float2 sred[2];

    for (int k = 0; k < NS; k++) {
        float2 f = g_T0[h][k * NS + n];
        gre[k][n] = f.x;
        gim[k][n] = f.y;
    }
    float2 cct = g_cct[h][n];
    float2 w = cct;
    __syncthreads();

    for (int it = 0; it < 24; it++) {
        sw[n] = w;
        __syncthreads();
        float2 acc = cct;
        #pragma unroll 4
        for (int i = 0; i < NS; i++) {
            float2 gi = make_float2(gre[i][n], gim[i][n]);
            float2 wi = sw[i];
            acc.x = fmaf(wi.x, gi.x, fmaf(-wi.y, gi.y, acc.x));
            acc.y = fmaf(wi.x, gi.y, fmaf(wi.y, gi.x, acc.y));
        }
        __syncthreads();
        w = acc;
    }
    float2 cb = w;
    g_cb[h][n] = cb;

    float2 m = g_m[h][n], v = g_v[h][n], r = g_r[h][n];
    float2 wr = cb;
    for (int tau = 0; tau < NS; tau++) {
        float2 dot = blockReduce64(cmul(wr, v), sred);
        wr = csub(cmul(m, wr), cmul(dot, r));
        g_Wt[h][n * NS + tau] = wr;
    }

    sw[n] = cb;
    __syncthreads();
    float acc = 0.0f;
    for (int i = 0; i < NS; i++) {
        float2 kp = g_K[h][n * NS + i];
        float2 ci = sw[i];
        acc += ci.x * kp.x - ci.y * kp.y;
    }
    g_taps[h][n] = acc;
}

// ---------------- kernel 4: chunk-local ends E + causal conv -> out ----------------
__global__ __launch_bounds__(256) void econv_kernel(const float* __restrict__ u,
                                                    const float* __restrict__ Din,
                                                    float* __restrict__ out) {
    int h = blockIdx.x;
    int t = threadIdx.x;
    __shared__ float su[LLEN];
    __shared__ float kre[NS][NS];
    __shared__ float kim[NS][NS];
    __shared__ float staps[NS];

    for (int i = t; i < LLEN; i += 256) su[i] = u[i * HN + h];
    for (int idx = t; idx < NS * NS; idx += 256) {
        float2 f = g_K[h][idx];
        kre[idx >> 6][idx & 63] = f.x;
        kim[idx >> 6][idx & 63] = f.y;
    }
    if (t < NS) staps[t] = g_taps[h][t];
    __syncthreads();

    float Dh = Din[h];
    int n = t & 63;
    int jb = t >> 6;
    for (int jj = 0; jj < 8; jj++) {
        int j = jb * 8 + jj;
        const float* uj = &su[j * 64];
        float er = 0.0f, ei = 0.0f;
        #pragma unroll 4
        for (int s = 0; s < 64; s++) {
            float us = uj[s];
            er = fmaf(kre[63 - s][n], us, er);
            ei = fmaf(kim[63 - s][n], us, ei);
        }
        g_E[h][j][n] = make_float2(er, ei);
        float yc = 0.0f;
        for (int s = 0; s <= n; s++) yc = fmaf(staps[n - s], uj[s], yc);
        int tg = j * 64 + n;
        out[tg * HN + h] = yc + Dh * su[tg];
    }
}

// ---------------- kernel 5: carry propagation with dense Ab^64 ----------------
__global__ void prop_kernel(const float* __restrict__ x0re, const float* __restrict__ x0im) {
    int h = blockIdx.x;
    int n = threadIdx.x;
    __shared__ float ar[NS][NS + 1];
    __shared__ float ai[NS][NS + 1];
    __shared__ float2 sx[NS];

    for (int k = 0; k < NS; k++) {
        float2 f = g_AB64[h][k * NS + n];
        ar[k][n] = f.x;
        ai[k][n] = f.y;
    }
    float2 x = make_float2(x0re[n * HN + h], x0im[n * HN + h]);
    __syncthreads();

    for (int j = 0; j < CHUNKS; j++) {
        g_XS[h][j][n] = x;
        sx[n] = x;
        __syncthreads();
        float2 acc = g_E[h][j][n];
        #pragma unroll 4
        for (int k = 0; k < NS; k++) {
            float2 a = make_float2(ar[n][k], ai[n][k]);
            float2 xk = sx[k];
            acc.x = fmaf(a.x, xk.x, fmaf(-a.y, xk.y, acc.x));
            acc.y = fmaf(a.x, xk.y, fmaf(a.y, xk.x, acc.y));
        }
        __syncthreads();
        x = acc;
    }
}

// ---------------- kernel 6: carry contribution Y1 -> out ----------------
__global__ __launch_bounds__(256) void y1_kernel(float* __restrict__ out) {
    int h = blockIdx.x;
    int t = threadIdx.x;
    __shared__ float wre[NS][NS];
    __shared__ float wim[NS][NS];

    for (int idx = t; idx < NS * NS; idx += 256) {
        float2 f = g_Wt[h][idx];
        wre[idx >> 6][idx & 63] = f.x;
        wim[idx >> 6][idx & 63] = f.y;
    }
    __syncthreads();

    int tau = t & 63;
    int jb = t >> 6;
    for (int jj = 0; jj < 8; jj++) {
        int j = jb * 8 + jj;
        float acc = 0.0f;
        #pragma unroll 4
        for (int n = 0; n < NS; n++) {
            float2 xs = g_XS[h][j][n];
            acc = fmaf(wre[n][tau], xs.x, fmaf(-wim[n][tau], xs.y, acc));
        }
        int tg = j * 64 + tau;
        out[tg * HN + h] += acc;
    }
}

// ---------------- launch ----------------
extern "C" void kernel_launch(void* const* d_in, const int* in_sizes, int n_in,
                              void* d_out, int out_size) {
    const float* u     = (const float*)d_in[0];
    const float* x0re  = (const float*)d_in[1];
    const float* x0im  = (const float*)d_in[2];
    const float* Lre   = (const float*)d_in[3];
    const float* Lim   = (const float*)d_in[4];
    const float* Pre   = (const float*)d_in[5];
    const float* Pim   = (const float*)d_in[6];
    const float* Bre   = (const float*)d_in[7];
    const float* Bim   = (const float*)d_in[8];
    const float* Cin   = (const float*)d_in[9];
    const float* Din   = (const float*)d_in[10];
    const float* lstep = (const float*)d_in[11];
    float* out = (float*)d_out;

    cudaFuncSetAttribute(powers_kernel, cudaFuncAttributeMaxDynamicSharedMemorySize, SM_BYTES);

    derive_kernel<<<HN, 64>>>(Lre, Lim, Pre, Pim, Bre, Bim, Cin, lstep);
    powers_kernel<<<HN, 256, SM_BYTES>>>();
    cbw_kernel<<<HN, 64>>>();
    econv_kernel<<<HN, 256>>>(u, Din, out);
    prop_kernel<<<HN, 64>>>(x0re, x0im);
    y1_kernel<<<HN, 256>>>(out);
}

// round 4
// speedup vs baseline: 1.2528x; 1.0851x over previous
#include <cuda_runtime.h>
#include <math.h>

#define HN 512
#define NS 64
#define LLEN 2048
#define CHUNKS 32

// ---------------- device scratch (no dynamic allocation) ----------------
__device__ float2 g_m[HN][NS];
__device__ float2 g_v[HN][NS];
__device__ float2 g_r[HN][NS];
__device__ float2 g_cct[HN][NS];
__device__ float2 g_cb[HN][NS];
__device__ float  g_taps[HN][NS];
__device__ float2 g_T0[HN][NS * NS];     // Ab, later Ab^2048
__device__ float2 g_AB64[HN][NS * NS];   // Ab^64
__device__ float2 g_K[HN][NS * NS];      // [p][n]
__device__ float2 g_Wt[HN][NS * NS];     // [n][tau]
__device__ float2 g_E[HN][CHUNKS][NS];
__device__ float2 g_XS[HN][CHUNKS][NS];

// ---------------- complex helpers ----------------
__device__ __forceinline__ float2 cmul(float2 a, float2 b) {
    return make_float2(a.x * b.x - a.y * b.y, a.x * b.y + a.y * b.x);
}
__device__ __forceinline__ float2 csub(float2 a, float2 b) { return make_float2(a.x - b.x, a.y - b.y); }
__device__ __forceinline__ float2 conj2(float2 a) { return make_float2(a.x, -a.y); }
__device__ __forceinline__ float2 crcp(float2 a) {
    float inv = 1.0f / (a.x * a.x + a.y * a.y);
    return make_float2(a.x * inv, -a.y * inv);
}

// f32x2 packed FMA: d += a * b (element-wise on 2 packed floats)
__device__ __forceinline__ void fma2(unsigned long long& d, unsigned long long a, unsigned long long b) {
    asm("fma.rn.f32x2 %0, %1, %2, %0;" : "+l"(d) : "l"(a), "l"(b));
}
__device__ __forceinline__ float2 u2f(unsigned long long u) {
    float2 f;
    asm("mov.b64 {%0, %1}, %2;" : "=f"(f.x), "=f"(f.y) : "l"(u));
    return f;
}
__device__ __forceinline__ unsigned long long packdup(float a) {
    unsigned long long r;
    asm("mov.b64 %0, {%1, %1};" : "=l"(r) : "f"(a));
    return r;
}

// 64-thread (2 warp) block reduction of a complex value.
__device__ __forceinline__ float2 blockReduce64(float2 val, float2* sbuf) {
    #pragma unroll
    for (int o = 16; o > 0; o >>= 1) {
        val.x += __shfl_xor_sync(0xffffffffu, val.x, o);
        val.y += __shfl_xor_sync(0xffffffffu, val.y, o);
    }
    int tid = threadIdx.x;
    if ((tid & 31) == 0) sbuf[tid >> 5] = val;
    __syncthreads();
    float2 res = make_float2(sbuf[0].x + sbuf[1].x, sbuf[0].y + sbuf[1].y);
    __syncthreads();
    return res;
}

// warp-level reduce of (dx,dy) across 32 lanes
__device__ __forceinline__ float2 warpReduce2(float dx, float dy) {
    #pragma unroll
    for (int o = 16; o > 0; o >>= 1) {
        dx += __shfl_xor_sync(0xffffffffu, dx, o);
        dy += __shfl_xor_sync(0xffffffffu, dy, o);
    }
    return make_float2(dx, dy);
}

// ---------------- kernel 1: derive params, dense Ab, K chain ----------------
__global__ void derive_kernel(const float* __restrict__ Lre, const float* __restrict__ Lim,
                              const float* __restrict__ Pre, const float* __restrict__ Pim,
                              const float* __restrict__ Bre, const float* __restrict__ Bim,
                              const float* __restrict__ Cin, const float* __restrict__ lstep) {
    int h = blockIdx.x;
    int n = threadIdx.x;
    __shared__ float2 sred[2];
    __shared__ float2 sr[NS];
    __shared__ float2 sm_m[NS], sm_v[NS], sm_bb[NS];

    float dt = expf(lstep[h]);
    float tdt = 2.0f / dt;
    float lre = fminf(Lre[h * NS + n], -1e-4f);
    float lim = Lim[h * NS + n];

    float2 den = make_float2(tdt - lre, -lim);
    float2 d = crcp(den);
    float2 a0 = make_float2(tdt + lre, lim);
    float2 m = cmul(d, a0);
    float2 P = make_float2(Pre[h * NS + n], Pim[h * NS + n]);
    float p2 = P.x * P.x + P.y * P.y;

    float2 s = blockReduce64(make_float2(p2 * d.x, p2 * d.y), sred);
    float2 c = crcp(make_float2(1.0f + s.x, s.y));
    float2 v = cmul(d, P);
    float2 onem = make_float2(1.0f + m.x, m.y);
    float2 r = cmul(c, cmul(conj2(P), onem));

    float2 B = make_float2(Bre[h * NS + n], Bim[h * NS + n]);
    float2 t1 = cmul(cmul(conj2(P), B), d);
    float2 sB = blockReduce64(t1, sred);
    float2 cs = cmul(c, sB);
    float2 dB = cmul(d, B);
    float2 vcs = cmul(cs, v);
    float2 bb = make_float2(2.0f * (dB.x - vcs.x), 2.0f * (dB.y - vcs.y));

    float2 cct = make_float2(Cin[h * 2 * NS + 2 * n], -Cin[h * 2 * NS + 2 * n + 1]);

    g_m[h][n] = m; g_v[h][n] = v; g_r[h][n] = r; g_cct[h][n] = cct;

    sr[n] = r; sm_m[n] = m; sm_v[n] = v; sm_bb[n] = bb;
    __syncthreads();
    // Dense Ab row n: Ab[n][j] = (n==j)m_n - v_n r_j
    #pragma unroll 4
    for (int j = 0; j < NS; j++) {
        float2 e = cmul(v, sr[j]);
        float2 val = make_float2(-e.x, -e.y);
        if (j == n) { val.x += m.x; val.y += m.y; }
        g_T0[h][n * NS + j] = val;
    }

    // K chain on warp 0 only: K_0 = Bb ; K_{p+1} = m*K_p - v*(r . K_p)
    if (n < 32) {
        float2 xa = sm_bb[n], xb = sm_bb[n + 32];
        float2 ra = sr[n], rb = sr[n + 32];
        float2 ma = sm_m[n], mb = sm_m[n + 32];
        float2 va = sm_v[n], vb = sm_v[n + 32];
        g_K[h][n] = xa; g_K[h][n + 32] = xb;
        for (int p = 1; p < NS; p++) {
            float2 d1 = cmul(ra, xa), d2 = cmul(rb, xb);
            float2 dot = warpReduce2(d1.x + d2.x, d1.y + d2.y);
            xa = csub(cmul(ma, xa), cmul(va, dot));
            xb = csub(cmul(mb, xb), cmul(vb, dot));
            g_K[h][p * NS + n] = xa;
            g_K[h][p * NS + n + 32] = xb;
        }
    }
}

// ---------------- kernel 2: fused 11 squarings, f32x2, 128 thr, 4x4-pair tiles ----------------
#define DROW 66
#define SM_BYTES (2 * 64 * DROW * 8 + 2 * 64 * DROW * 4)

__global__ __launch_bounds__(128, 2) void powers_kernel() {
    extern __shared__ char smraw[];
    float2* are_dup = (float2*)smraw;
    float2* aim_dup = are_dup + 64 * DROW;
    float*  brem    = (float*)(aim_dup + 64 * DROW);
    float*  bimm    = brem + 64 * DROW;

    int h = blockIdx.x;
    int t = threadIdx.x;

    for (int idx = t; idx < NS * NS; idx += 128) {
        int r = idx >> 6, c = idx & 63;
        float2 f = g_T0[h][idx];
        brem[r * DROW + c] = f.x;
        bimm[r * DROW + c] = f.y;
        are_dup[c * DROW + r] = make_float2(f.x, f.x);
        aim_dup[c * DROW + r] = make_float2(f.y, f.y);
    }
    __syncthreads();

    int r0 = (t >> 3) * 4;      // 16 row-groups of 4
    int ci = t & 7;             // 8 col-groups; pairs at 2ci + 16p, p=0..3

    for (int step = 0; step < 11; step++) {
        unsigned long long accRR[4][4] = {}, accII[4][4] = {}, accRI[4][4] = {}, accIR[4][4] = {};

        #pragma unroll 4
        for (int k = 0; k < NS; k++) {
            unsigned long long a_re[4], a_im[4];
            #pragma unroll
            for (int i = 0; i < 4; i++) {
                a_re[i] = *(const unsigned long long*)&are_dup[k * DROW + r0 + i];
                a_im[i] = *(const unsigned long long*)&aim_dup[k * DROW + r0 + i];
            }
            unsigned long long b_re[4], b_im[4];
            #pragma unroll
            for (int p = 0; p < 4; p++) {
                b_re[p] = *(const unsigned long long*)&brem[k * DROW + 2 * ci + 16 * p];
                b_im[p] = *(const unsigned long long*)&bimm[k * DROW + 2 * ci + 16 * p];
            }
            #pragma unroll
            for (int i = 0; i < 4; i++)
                #pragma unroll
                for (int p = 0; p < 4; p++) {
                    fma2(accRR[i][p], a_re[i], b_re[p]);
                    fma2(accII[i][p], a_im[i], b_im[p]);
                    fma2(accRI[i][p], a_re[i], b_im[p]);
                    fma2(accIR[i][p], a_im[i], b_re[p]);
                }
        }
        __syncthreads();

        bool save64 = (step == 5);
        bool save2048 = (step == 10);
        #pragma unroll
        for (int i = 0; i < 4; i++) {
            #pragma unroll
            for (int p = 0; p < 4; p++) {
                float2 rr = u2f(accRR[i][p]);
                float2 ii = u2f(accII[i][p]);
                float2 rim = u2f(accRI[i][p]);
                float2 ir = u2f(accIR[i][p]);
                float re0 = rr.x - ii.x, re1 = rr.y - ii.y;
                float im0 = rim.x + ir.x, im1 = rim.y + ir.y;
                int r = r0 + i;
                int j = 2 * ci + 16 * p;
                brem[r * DROW + j] = re0;     brem[r * DROW + j + 1] = re1;
                bimm[r * DROW + j] = im0;     bimm[r * DROW + j + 1] = im1;
                are_dup[j * DROW + r] = make_float2(re0, re0);
                are_dup[(j + 1) * DROW + r] = make_float2(re1, re1);
                aim_dup[j * DROW + r] = make_float2(im0, im0);
                aim_dup[(j + 1) * DROW + r] = make_float2(im1, im1);
                if (save64) {
                    g_AB64[h][r * NS + j] = make_float2(re0, im0);
                    g_AB64[h][r * NS + j + 1] = make_float2(re1, im1);
                }
                if (save2048) {
                    g_T0[h][r * NS + j] = make_float2(re0, im0);
                    g_T0[h][r * NS + j + 1] = make_float2(re1, im1);
                }
            }
        }
        __syncthreads();
    }
}

// ---------------- kernel 3: Cb (Neumann), Wt chain (warp), taps ----------------
__global__ void cbw_kernel() {
    int h = blockIdx.x;
    int n = threadIdx.x;
    __shared__ float gre[NS][NS + 1];
    __shared__ float gim[NS][NS + 1];
    __shared__ float2 sw[NS];
    __shared__ float2 scb[NS];

    for (int k = 0; k < NS; k++) {
        float2 f = g_T0[h][k * NS + n];
        gre[k][n] = f.x;
        gim[k][n] = f.y;
    }
    float2 cct = g_cct[h][n];
    float2 w = cct;
    __syncthreads();

    for (int it = 0; it < 22; it++) {
        sw[n] = w;
        __syncthreads();
        float2 acc = cct;
        #pragma unroll 4
        for (int i = 0; i < NS; i++) {
            float2 gi = make_float2(gre[i][n], gim[i][n]);
            float2 wi = sw[i];
            acc.x = fmaf(wi.x, gi.x, fmaf(-wi.y, gi.y, acc.x));
            acc.y = fmaf(wi.x, gi.y, fmaf(wi.y, gi.x, acc.y));
        }
        __syncthreads();
        w = acc;
    }
    float2 cb = w;
    g_cb[h][n] = cb;
    scb[n] = cb;
    __syncthreads();

    if (n < 32) {
        // Wt chain on warp 0: wr <- m*wr - (wr . v) r ; store Wt[n][tau]
        float2 wa = scb[n], wb = scb[n + 32];
        float2 ma = g_m[h][n], mb = g_m[h][n + 32];
        float2 va = g_v[h][n], vb = g_v[h][n + 32];
        float2 ra = g_r[h][n], rb = g_r[h][n + 32];
        for (int tau = 0; tau < NS; tau++) {
            float2 d1 = cmul(wa, va), d2 = cmul(wb, vb);
            float2 dot = warpReduce2(d1.x + d2.x, d1.y + d2.y);
            wa = csub(cmul(ma, wa), cmul(dot, ra));
            wb = csub(cmul(mb, wb), cmul(dot, rb));
            g_Wt[h][n * NS + tau] = wa;
            g_Wt[h][(n + 32) * NS + tau] = wb;
        }
    } else {
        // warp 1: taps for p = 32..63 concurrently
        int p = n;
        float acc = 0.0f;
        for (int i = 0; i < NS; i++) {
            float2 kp = g_K[h][p * NS + i];
            float2 ci = scb[i];
            acc = fmaf(ci.x, kp.x, fmaf(-ci.y, kp.y, acc));
        }
        g_taps[h][p] = acc;
    }
    if (n < 32) {
        int p = n;
        float acc = 0.0f;
        for (int i = 0; i < NS; i++) {
            float2 kp = g_K[h][p * NS + i];
            float2 ci = scb[i];
            acc = fmaf(ci.x, kp.x, fmaf(-ci.y, kp.y, acc));
        }
        g_taps[h][p] = acc;
    }
}

// ---------------- kernel 4: chunk-local ends E + causal conv -> out ----------------
__global__ __launch_bounds__(256) void econv_kernel(const float* __restrict__ u,
                                                    const float* __restrict__ Din,
                                                    float* __restrict__ out) {
    int h = blockIdx.x;
    int t = threadIdx.x;
    __shared__ float su[LLEN];                 // 8KB
    __shared__ float2 kc[NS][NS];              // 32KB: (re,im) of K[p][n]
    __shared__ float stp[2 * NS];              // padded taps

    for (int i = t; i < LLEN; i += 256) su[i] = u[i * HN + h];
    for (int idx = t; idx < NS * NS; idx += 256) kc[idx >> 6][idx & 63] = g_K[h][idx];
    if (t < NS) { stp[t] = 0.0f; stp[NS + t] = g_taps[h][t]; }
    __syncthreads();

    float Dh = Din[h];
    int n = t & 63;
    int jb = t >> 6;
    for (int jj = 0; jj < 8; jj++) {
        int j = jb * 8 + jj;
        const float* uj = &su[j * 64];
        unsigned long long acc2a = 0ull, acc2b = 0ull;
        float yc0 = 0.0f, yc1 = 0.0f;
        #pragma unroll 8
        for (int s = 0; s < 64; s += 2) {
            float us0 = uj[s], us1 = uj[s + 1];
            fma2(acc2a, *(const unsigned long long*)&kc[63 - s][n], packdup(us0));
            fma2(acc2b, *(const unsigned long long*)&kc[62 - s][n], packdup(us1));
            yc0 = fmaf(stp[NS + n - s], us0, yc0);
            yc1 = fmaf(stp[NS + n - s - 1], us1, yc1);
        }
        float2 ea = u2f(acc2a), eb = u2f(acc2b);
        g_E[h][j][n] = make_float2(ea.x + eb.x, ea.y + eb.y);
        int tg = j * 64 + n;
        out[tg * HN + h] = yc0 + yc1 + Dh * su[tg];
    }
}

// ---------------- kernel 5: carry propagation, 256 threads, k split 4-way ----------------
__global__ __launch_bounds__(256) void prop_kernel(const float* __restrict__ x0re, const float* __restrict__ x0im) {
    int h = blockIdx.x;
    int t = threadIdx.x;
    int n = t & 63;
    int q = t >> 6;            // k-quarter 0..3
    __shared__ float ar[NS][NS + 1];
    __shared__ float ai[NS][NS + 1];
    __shared__ float2 sx[NS];
    __shared__ float2 spart[4][NS];

    for (int idx = t; idx < NS * NS; idx += 256) {
        int r = idx >> 6, c = idx & 63;
        float2 f = g_AB64[h][idx];
        ar[r][c] = f.x;
        ai[r][c] = f.y;
    }
    float2 x;
    if (q == 0) {
        x = make_float2(x0re[n * HN + h], x0im[n * HN + h]);
        sx[n] = x;
    }
    __syncthreads();

    int k0 = q * 16;
    for (int j = 0; j < CHUNKS; j++) {
        if (q == 0) g_XS[h][j][n] = x;
        float2 acc = make_float2(0.0f, 0.0f);
        #pragma unroll
        for (int kk = 0; kk < 16; kk++) {
            int k = k0 + kk;
            float arr = ar[n][k], aii = ai[n][k];
            float2 xk = sx[k];
            acc.x = fmaf(arr, xk.x, fmaf(-aii, xk.y, acc.x));
            acc.y = fmaf(arr, xk.y, fmaf(aii, xk.x, acc.y));
        }
        spart[q][n] = acc;
        __syncthreads();
        if (q == 0) {
            float2 e = g_E[h][j][n];
            x.x = e.x + spart[0][n].x + spart[1][n].x + spart[2][n].x + spart[3][n].x;
            x.y = e.y + spart[0][n].y + spart[1][n].y + spart[2][n].y + spart[3][n].y;
            sx[n] = x;
        }
        __syncthreads();
    }
}

// ---------------- kernel 6: carry contribution Y1 -> out ----------------
__global__ __launch_bounds__(256) void y1_kernel(float* __restrict__ out) {
    int h = blockIdx.x;
    int t = threadIdx.x;
    __shared__ float2 wc[NS][NS];          // 32KB: (re,im) of Wt[n][tau]
    __shared__ float2 xs2[CHUNKS][NS];     // 16KB: (x, -y)

    for (int idx = t; idx < NS * NS; idx += 256) wc[idx >> 6][idx & 63] = g_Wt[h][idx];
    for (int idx = t; idx < CHUNKS * NS; idx += 256) {
        float2 f = g_XS[h][idx >> 6][idx & 63];
        xs2[idx >> 6][idx & 63] = make_float2(f.x, -f.y);
    }
    __syncthreads();

    int tau = t & 63;
    int jb = t >> 6;
    for (int jj = 0; jj < 8; jj++) {
        int j = jb * 8 + jj;
        unsigned long long acc2 = 0ull;
        #pragma unroll 8
        for (int n = 0; n < NS; n++) {
            fma2(acc2, *(const unsigned long long*)&wc[n][tau], *(const unsigned long long*)&xs2[j][n]);
        }
        float2 f = u2f(acc2);
        int tg = j * 64 + tau;
        out[tg * HN + h] += f.x + f.y;
    }
}

// ---------------- launch ----------------
extern "C" void kernel_launch(void* const* d_in, const int* in_sizes, int n_in,
                              void* d_out, int out_size) {
    const float* u     = (const float*)d_in[0];
    const float* x0re  = (const float*)d_in[1];
    const float* x0im  = (const float*)d_in[2];
    const float* Lre   = (const float*)d_in[3];
    const float* Lim   = (const float*)d_in[4];
    const float* Pre   = (const float*)d_in[5];
    const float* Pim   = (const float*)d_in[6];
    const float* Bre   = (const float*)d_in[7];
    const float* Bim   = (const float*)d_in[8];
    const float* Cin   = (const float*)d_in[9];
    const float* Din   = (const float*)d_in[10];
    const float* lstep = (const float*)d_in[11];
    float* out = (float*)d_out;

    cudaFuncSetAttribute(powers_kernel, cudaFuncAttributeMaxDynamicSharedMemorySize, SM_BYTES);

    derive_kernel<<<HN, 64>>>(Lre, Lim, Pre, Pim, Bre, Bim, Cin, lstep);
    powers_kernel<<<HN, 128, SM_BYTES>>>();
    cbw_kernel<<<HN, 64>>>();
    econv_kernel<<<HN, 256>>>(u, Din, out);
    prop_kernel<<<HN, 256>>>(x0re, x0im);
    y1_kernel<<<HN, 256>>>(out);
}

// round 5
// speedup vs baseline: 1.3645x; 1.0892x over previous
#include <cuda_runtime.h>
#include <math.h>

#define HN 512
#define NS 64
#define LLEN 2048
#define CHUNKS 32

// ---------------- device scratch (no dynamic allocation) ----------------
__device__ float2 g_m[HN][NS];
__device__ float2 g_v[HN][NS];
__device__ float2 g_r[HN][NS];
__device__ float2 g_cct[HN][NS];
__device__ float  g_taps[HN][NS];
__device__ float2 g_T0[HN][NS * NS];     // A^64 (from a64_kernel), later A^2048
__device__ float2 g_AB64[HN][NS * NS];   // A^64
__device__ float2 g_K[HN][NS * NS];      // [p][n]
__device__ float2 g_Wt[HN][NS * NS];     // [n][tau]
__device__ float2 g_E[HN][CHUNKS][NS];
__device__ float2 g_XS[HN][CHUNKS][NS];

// ---------------- complex helpers ----------------
__device__ __forceinline__ float2 cmul(float2 a, float2 b) {
    return make_float2(a.x * b.x - a.y * b.y, a.x * b.y + a.y * b.x);
}
__device__ __forceinline__ float2 csub(float2 a, float2 b) { return make_float2(a.x - b.x, a.y - b.y); }
__device__ __forceinline__ float2 conj2(float2 a) { return make_float2(a.x, -a.y); }
__device__ __forceinline__ float2 crcp(float2 a) {
    float inv = 1.0f / (a.x * a.x + a.y * a.y);
    return make_float2(a.x * inv, -a.y * inv);
}

// f32x2 packed FMA: d += a * b (element-wise on 2 packed floats)
__device__ __forceinline__ void fma2(unsigned long long& d, unsigned long long a, unsigned long long b) {
    asm("fma.rn.f32x2 %0, %1, %2, %0;" : "+l"(d) : "l"(a), "l"(b));
}
__device__ __forceinline__ float2 u2f(unsigned long long u) {
    float2 f;
    asm("mov.b64 {%0, %1}, %2;" : "=f"(f.x), "=f"(f.y) : "l"(u));
    return f;
}
__device__ __forceinline__ unsigned long long packdup(float a) {
    unsigned long long r;
    asm("mov.b64 %0, {%1, %1};" : "=l"(r) : "f"(a));
    return r;
}

// 64-thread (2 warp) block reduction of a complex value.
__device__ __forceinline__ float2 blockReduce64(float2 val, float2* sbuf) {
    #pragma unroll
    for (int o = 16; o > 0; o >>= 1) {
        val.x += __shfl_xor_sync(0xffffffffu, val.x, o);
        val.y += __shfl_xor_sync(0xffffffffu, val.y, o);
    }
    int tid = threadIdx.x;
    if ((tid & 31) == 0) sbuf[tid >> 5] = val;
    __syncthreads();
    float2 res = make_float2(sbuf[0].x + sbuf[1].x, sbuf[0].y + sbuf[1].y);
    __syncthreads();
    return res;
}

// warp-level reduce of (dx,dy) across 32 lanes
__device__ __forceinline__ float2 warpReduce2(float dx, float dy) {
    #pragma unroll
    for (int o = 16; o > 0; o >>= 1) {
        dx += __shfl_xor_sync(0xffffffffu, dx, o);
        dy += __shfl_xor_sync(0xffffffffu, dy, o);
    }
    return make_float2(dx, dy);
}

// ---------------- kernel 1: derive params + K chain ----------------
__global__ void derive_kernel(const float* __restrict__ Lre, const float* __restrict__ Lim,
                              const float* __restrict__ Pre, const float* __restrict__ Pim,
                              const float* __restrict__ Bre, const float* __restrict__ Bim,
                              const float* __restrict__ Cin, const float* __restrict__ lstep) {
    int h = blockIdx.x;
    int n = threadIdx.x;
    __shared__ float2 sred[2];
    __shared__ float2 sr[NS];
    __shared__ float2 sm_m[NS], sm_v[NS], sm_bb[NS];

    float dt = expf(lstep[h]);
    float tdt = 2.0f / dt;
    float lre = fminf(Lre[h * NS + n], -1e-4f);
    float lim = Lim[h * NS + n];

    float2 den = make_float2(tdt - lre, -lim);
    float2 d = crcp(den);
    float2 a0 = make_float2(tdt + lre, lim);
    float2 m = cmul(d, a0);
    float2 P = make_float2(Pre[h * NS + n], Pim[h * NS + n]);
    float p2 = P.x * P.x + P.y * P.y;

    float2 s = blockReduce64(make_float2(p2 * d.x, p2 * d.y), sred);
    float2 c = crcp(make_float2(1.0f + s.x, s.y));
    float2 v = cmul(d, P);
    float2 onem = make_float2(1.0f + m.x, m.y);
    float2 r = cmul(c, cmul(conj2(P), onem));

    float2 B = make_float2(Bre[h * NS + n], Bim[h * NS + n]);
    float2 t1 = cmul(cmul(conj2(P), B), d);
    float2 sB = blockReduce64(t1, sred);
    float2 cs = cmul(c, sB);
    float2 dB = cmul(d, B);
    float2 vcs = cmul(cs, v);
    float2 bb = make_float2(2.0f * (dB.x - vcs.x), 2.0f * (dB.y - vcs.y));

    float2 cct = make_float2(Cin[h * 2 * NS + 2 * n], -Cin[h * 2 * NS + 2 * n + 1]);

    g_m[h][n] = m; g_v[h][n] = v; g_r[h][n] = r; g_cct[h][n] = cct;

    sr[n] = r; sm_m[n] = m; sm_v[n] = v; sm_bb[n] = bb;
    __syncthreads();

    // K chain on warp 0 only: K_0 = Bb ; K_{p+1} = m*K_p - v*(r . K_p)
    if (n < 32) {
        float2 xa = sm_bb[n], xb = sm_bb[n + 32];
        float2 ra = sr[n], rb = sr[n + 32];
        float2 ma = sm_m[n], mb = sm_m[n + 32];
        float2 va = sm_v[n], vb = sm_v[n + 32];
        g_K[h][n] = xa; g_K[h][n + 32] = xb;
        for (int p = 1; p < NS; p++) {
            float2 d1 = cmul(ra, xa), d2 = cmul(rb, xb);
            float2 dot = warpReduce2(d1.x + d2.x, d1.y + d2.y);
            xa = csub(cmul(ma, xa), cmul(va, dot));
            xb = csub(cmul(mb, xb), cmul(vb, dot));
            g_K[h][p * NS + n] = xa;
            g_K[h][p * NS + n + 32] = xb;
        }
    }
}

// ---------------- kernel 2: A^64 via 63 structured steps M <- D*M - v*(r^T M) ----------------
__global__ __launch_bounds__(256) void a64_kernel() {
    int h = blockIdx.x;
    int t = threadIdx.x;
    int j = t & 63;
    int q = t >> 6;
    __shared__ float2 sM[NS][NS + 1];
    __shared__ float2 srm[NS], smm[NS], svm[NS];
    __shared__ float2 spart[4][NS];

    if (t < NS) { srm[t] = g_r[h][t]; smm[t] = g_m[h][t]; svm[t] = g_v[h][t]; }
    __syncthreads();

    // init M = A : M[n][j] = delta*m_n - v_n r_j
    {
        float2 rj = srm[j];
        #pragma unroll
        for (int k = 0; k < 16; k++) {
            int n = q * 16 + k;
            float2 e = cmul(svm[n], rj);
            float2 val = make_float2(-e.x, -e.y);
            if (n == j) { val.x += smm[n].x; val.y += smm[n].y; }
            sM[n][j] = val;
        }
    }
    __syncthreads();

    for (int it = 0; it < 63; it++) {
        float2 Mreg[16];
        float2 acc = make_float2(0.0f, 0.0f);
        #pragma unroll
        for (int k = 0; k < 16; k++) {
            int n = q * 16 + k;
            Mreg[k] = sM[n][j];
            float2 rn = srm[n];
            acc.x = fmaf(rn.x, Mreg[k].x, fmaf(-rn.y, Mreg[k].y, acc.x));
            acc.y = fmaf(rn.x, Mreg[k].y, fmaf(rn.y, Mreg[k].x, acc.y));
        }
        spart[q][j] = acc;
        __syncthreads();
        float2 w;
        w.x = spart[0][j].x + spart[1][j].x + spart[2][j].x + spart[3][j].x;
        w.y = spart[0][j].y + spart[1][j].y + spart[2][j].y + spart[3][j].y;
        #pragma unroll
        for (int k = 0; k < 16; k++) {
            int n = q * 16 + k;
            float2 mn = smm[n], vn = svm[n];
            float2 nv;
            nv.x = mn.x * Mreg[k].x - mn.y * Mreg[k].y - (vn.x * w.x - vn.y * w.y);
            nv.y = mn.x * Mreg[k].y + mn.y * Mreg[k].x - (vn.x * w.y + vn.y * w.x);
            sM[n][j] = nv;
        }
        __syncthreads();
    }

    #pragma unroll
    for (int k = 0; k < 16; k++) {
        int n = q * 16 + k;
        float2 val = sM[n][j];
        g_AB64[h][n * NS + j] = val;
        g_T0[h][n * NS + j] = val;
    }
}

// ---------------- kernel 3: 5 fused squarings A^64 -> A^2048, f32x2 ----------------
#define DROW 66
#define SM_BYTES (2 * 64 * DROW * 8 + 2 * 64 * DROW * 4)

__global__ __launch_bounds__(128, 2) void powers_kernel() {
    extern __shared__ char smraw[];
    float2* are_dup = (float2*)smraw;
    float2* aim_dup = are_dup + 64 * DROW;
    float*  brem    = (float*)(aim_dup + 64 * DROW);
    float*  bimm    = brem + 64 * DROW;

    int h = blockIdx.x;
    int t = threadIdx.x;

    for (int idx = t; idx < NS * NS; idx += 128) {
        int r = idx >> 6, c = idx & 63;
        float2 f = g_T0[h][idx];
        brem[r * DROW + c] = f.x;
        bimm[r * DROW + c] = f.y;
        are_dup[c * DROW + r] = make_float2(f.x, f.x);
        aim_dup[c * DROW + r] = make_float2(f.y, f.y);
    }
    __syncthreads();

    int r0 = (t >> 3) * 4;      // 16 row-groups of 4
    int ci = t & 7;             // 8 col-groups; pairs at 2ci + 16p, p=0..3

    for (int step = 0; step < 5; step++) {
        unsigned long long accRR[4][4] = {}, accII[4][4] = {}, accRI[4][4] = {}, accIR[4][4] = {};

        #pragma unroll 4
        for (int k = 0; k < NS; k++) {
            unsigned long long a_re[4], a_im[4];
            #pragma unroll
            for (int i = 0; i < 4; i++) {
                a_re[i] = *(const unsigned long long*)&are_dup[k * DROW + r0 + i];
                a_im[i] = *(const unsigned long long*)&aim_dup[k * DROW + r0 + i];
            }
            unsigned long long b_re[4], b_im[4];
            #pragma unroll
            for (int p = 0; p < 4; p++) {
                b_re[p] = *(const unsigned long long*)&brem[k * DROW + 2 * ci + 16 * p];
                b_im[p] = *(const unsigned long long*)&bimm[k * DROW + 2 * ci + 16 * p];
            }
            #pragma unroll
            for (int i = 0; i < 4; i++)
                #pragma unroll
                for (int p = 0; p < 4; p++) {
                    fma2(accRR[i][p], a_re[i], b_re[p]);
                    fma2(accII[i][p], a_im[i], b_im[p]);
                    fma2(accRI[i][p], a_re[i], b_im[p]);
                    fma2(accIR[i][p], a_im[i], b_re[p]);
                }
        }
        __syncthreads();

        bool save2048 = (step == 4);
        #pragma unroll
        for (int i = 0; i < 4; i++) {
            #pragma unroll
            for (int p = 0; p < 4; p++) {
                float2 rr = u2f(accRR[i][p]);
                float2 ii = u2f(accII[i][p]);
                float2 rim = u2f(accRI[i][p]);
                float2 ir = u2f(accIR[i][p]);
                float re0 = rr.x - ii.x, re1 = rr.y - ii.y;
                float im0 = rim.x + ir.x, im1 = rim.y + ir.y;
                int r = r0 + i;
                int j = 2 * ci + 16 * p;
                if (save2048) {
                    g_T0[h][r * NS + j] = make_float2(re0, im0);
                    g_T0[h][r * NS + j + 1] = make_float2(re1, im1);
                } else {
                    brem[r * DROW + j] = re0;     brem[r * DROW + j + 1] = re1;
                    bimm[r * DROW + j] = im0;     bimm[r * DROW + j + 1] = im1;
                    are_dup[j * DROW + r] = make_float2(re0, re0);
                    are_dup[(j + 1) * DROW + r] = make_float2(re1, re1);
                    aim_dup[j * DROW + r] = make_float2(im0, im0);
                    aim_dup[(j + 1) * DROW + r] = make_float2(im1, im1);
                }
            }
        }
        __syncthreads();
    }
}

// ---------------- kernel 4: Cb (Neumann), Wt chain (warp), taps ----------------
__global__ void cbw_kernel() {
    int h = blockIdx.x;
    int n = threadIdx.x;
    __shared__ float gre[NS][NS + 1];
    __shared__ float gim[NS][NS + 1];
    __shared__ float2 sw[NS];
    __shared__ float2 scb[NS];

    for (int k = 0; k < NS; k++) {
        float2 f = g_T0[h][k * NS + n];
        gre[k][n] = f.x;
        gim[k][n] = f.y;
    }
    float2 cct = g_cct[h][n];
    float2 w = cct;
    __syncthreads();

    for (int it = 0; it < 22; it++) {
        sw[n] = w;
        __syncthreads();
        float2 acc = cct;
        #pragma unroll 4
        for (int i = 0; i < NS; i++) {
            float2 gi = make_float2(gre[i][n], gim[i][n]);
            float2 wi = sw[i];
            acc.x = fmaf(wi.x, gi.x, fmaf(-wi.y, gi.y, acc.x));
            acc.y = fmaf(wi.x, gi.y, fmaf(wi.y, gi.x, acc.y));
        }
        __syncthreads();
        w = acc;
    }
    float2 cb = w;
    scb[n] = cb;
    __syncthreads();

    if (n < 32) {
        // Wt chain on warp 0: wr <- m*wr - (wr . v) r ; store Wt[n][tau]
        float2 wa = scb[n], wb = scb[n + 32];
        float2 ma = g_m[h][n], mb = g_m[h][n + 32];
        float2 va = g_v[h][n], vb = g_v[h][n + 32];
        float2 ra = g_r[h][n], rb = g_r[h][n + 32];
        for (int tau = 0; tau < NS; tau++) {
            float2 d1 = cmul(wa, va), d2 = cmul(wb, vb);
            float2 dot = warpReduce2(d1.x + d2.x, d1.y + d2.y);
            wa = csub(cmul(ma, wa), cmul(dot, ra));
            wb = csub(cmul(mb, wb), cmul(dot, rb));
            g_Wt[h][n * NS + tau] = wa;
            g_Wt[h][(n + 32) * NS + tau] = wb;
        }
        // taps for p = 0..31
        int p = n;
        float acc = 0.0f;
        for (int i = 0; i < NS; i++) {
            float2 kp = g_K[h][p * NS + i];
            float2 ci = scb[i];
            acc = fmaf(ci.x, kp.x, fmaf(-ci.y, kp.y, acc));
        }
        g_taps[h][p] = acc;
    } else {
        // warp 1: taps for p = 32..63 concurrently
        int p = n;
        float acc = 0.0f;
        for (int i = 0; i < NS; i++) {
            float2 kp = g_K[h][p * NS + i];
            float2 ci = scb[i];
            acc = fmaf(ci.x, kp.x, fmaf(-ci.y, kp.y, acc));
        }
        g_taps[h][p] = acc;
    }
}

// ---------------- kernel 5: chunk-local ends E + causal conv -> out ----------------
__global__ __launch_bounds__(256) void econv_kernel(const float* __restrict__ u,
                                                    const float* __restrict__ Din,
                                                    float* __restrict__ out) {
    int h = blockIdx.x;
    int t = threadIdx.x;
    __shared__ float su[LLEN];                 // 8KB
    __shared__ float2 kc[NS][NS];              // 32KB: (re,im) of K[p][n]
    __shared__ float stp[2 * NS];              // padded taps

    for (int i = t; i < LLEN; i += 256) su[i] = u[i * HN + h];
    for (int idx = t; idx < NS * NS; idx += 256) kc[idx >> 6][idx & 63] = g_K[h][idx];
    if (t < NS) { stp[t] = 0.0f; stp[NS + t] = g_taps[h][t]; }
    __syncthreads();

    float Dh = Din[h];
    int n = t & 63;
    int jb = t >> 6;
    for (int jj = 0; jj < 8; jj++) {
        int j = jb * 8 + jj;
        const float* uj = &su[j * 64];
        unsigned long long acc2a = 0ull, acc2b = 0ull, acc2c = 0ull, acc2d = 0ull;
        float yc0 = 0.0f, yc1 = 0.0f, yc2 = 0.0f, yc3 = 0.0f;
        #pragma unroll 4
        for (int s = 0; s < 64; s += 4) {
            float us0 = uj[s], us1 = uj[s + 1], us2 = uj[s + 2], us3 = uj[s + 3];
            fma2(acc2a, *(const unsigned long long*)&kc[63 - s][n], packdup(us0));
            fma2(acc2b, *(const unsigned long long*)&kc[62 - s][n], packdup(us1));
            fma2(acc2c, *(const unsigned long long*)&kc[61 - s][n], packdup(us2));
            fma2(acc2d, *(const unsigned long long*)&kc[60 - s][n], packdup(us3));
            yc0 = fmaf(stp[NS + n - s], us0, yc0);
            yc1 = fmaf(stp[NS + n - s - 1], us1, yc1);
            yc2 = fmaf(stp[NS + n - s - 2], us2, yc2);
            yc3 = fmaf(stp[NS + n - s - 3], us3, yc3);
        }
        float2 ea = u2f(acc2a), eb = u2f(acc2b), ec = u2f(acc2c), ed = u2f(acc2d);
        g_E[h][j][n] = make_float2(ea.x + eb.x + ec.x + ed.x, ea.y + eb.y + ec.y + ed.y);
        int tg = j * 64 + n;
        out[tg * HN + h] = (yc0 + yc1) + (yc2 + yc3) + Dh * su[tg];
    }
}

// ---------------- kernel 6: carry propagation, 256 threads, k split 4-way ----------------
__global__ __launch_bounds__(256) void prop_kernel(const float* __restrict__ x0re, const float* __restrict__ x0im) {
    int h = blockIdx.x;
    int t = threadIdx.x;
    int n = t & 63;
    int q = t >> 6;            // k-quarter 0..3
    __shared__ float ar[NS][NS + 1];
    __shared__ float ai[NS][NS + 1];
    __shared__ float2 sx[NS];
    __shared__ float2 spart[4][NS];

    for (int idx = t; idx < NS * NS; idx += 256) {
        int r = idx >> 6, c = idx & 63;
        float2 f = g_AB64[h][idx];
        ar[r][c] = f.x;
        ai[r][c] = f.y;
    }
    float2 x;
    if (q == 0) {
        x = make_float2(x0re[n * HN + h], x0im[n * HN + h]);
        sx[n] = x;
    }
    __syncthreads();

    int k0 = q * 16;
    for (int j = 0; j < CHUNKS; j++) {
        if (q == 0) g_XS[h][j][n] = x;
        float2 acc = make_float2(0.0f, 0.0f);
        #pragma unroll
        for (int kk = 0; kk < 16; kk++) {
            int k = k0 + kk;
            float arr = ar[n][k], aii = ai[n][k];
            float2 xk = sx[k];
            acc.x = fmaf(arr, xk.x, fmaf(-aii, xk.y, acc.x));
            acc.y = fmaf(arr, xk.y, fmaf(aii, xk.x, acc.y));
        }
        spart[q][n] = acc;
        __syncthreads();
        if (q == 0) {
            float2 e = g_E[h][j][n];
            x.x = e.x + spart[0][n].x + spart[1][n].x + spart[2][n].x + spart[3][n].x;
            x.y = e.y + spart[0][n].y + spart[1][n].y + spart[2][n].y + spart[3][n].y;
            sx[n] = x;
        }
        __syncthreads();
    }
}

// ---------------- kernel 7: carry contribution Y1 -> out ----------------
__global__ __launch_bounds__(256) void y1_kernel(float* __restrict__ out) {
    int h = blockIdx.x;
    int t = threadIdx.x;
    __shared__ float2 wc[NS][NS];          // 32KB: (re,im) of Wt[n][tau]
    __shared__ float2 xs2[CHUNKS][NS];     // 16KB: (x, -y)

    for (int idx = t; idx < NS * NS; idx += 256) wc[idx >> 6][idx & 63] = g_Wt[h][idx];
    for (int idx = t; idx < CHUNKS * NS; idx += 256) {
        float2 f = g_XS[h][idx >> 6][idx & 63];
        xs2[idx >> 6][idx & 63] = make_float2(f.x, -f.y);
    }
    __syncthreads();

    int tau = t & 63;
    int jb = t >> 6;
    for (int jj = 0; jj < 8; jj++) {
        int j = jb * 8 + jj;
        unsigned long long acc2 = 0ull, acc2b = 0ull;
        #pragma unroll 8
        for (int n = 0; n < NS; n += 2) {
            fma2(acc2, *(const unsigned long long*)&wc[n][tau], *(const unsigned long long*)&xs2[j][n]);
            fma2(acc2b, *(const unsigned long long*)&wc[n + 1][tau], *(const unsigned long long*)&xs2[j][n + 1]);
        }
        float2 f = u2f(acc2);
        float2 fb = u2f(acc2b);
        int tg = j * 64 + tau;
        out[tg * HN + h] += (f.x + f.y) + (fb.x + fb.y);
    }
}

// ---------------- launch ----------------
extern "C" void kernel_launch(void* const* d_in, const int* in_sizes, int n_in,
                              void* d_out, int out_size) {
    const float* u     = (const float*)d_in[0];
    const float* x0re  = (const float*)d_in[1];
    const float* x0im  = (const float*)d_in[2];
    const float* Lre   = (const float*)d_in[3];
    const float* Lim   = (const float*)d_in[4];
    const float* Pre   = (const float*)d_in[5];
    const float* Pim   = (const float*)d_in[6];
    const float* Bre   = (const float*)d_in[7];
    const float* Bim   = (const float*)d_in[8];
    const float* Cin   = (const float*)d_in[9];
    const float* Din   = (const float*)d_in[10];
    const float* lstep = (const float*)d_in[11];
    float* out = (float*)d_out;

    cudaFuncSetAttribute(powers_kernel, cudaFuncAttributeMaxDynamicSharedMemorySize, SM_BYTES);

    derive_kernel<<<HN, 64>>>(Lre, Lim, Pre, Pim, Bre, Bim, Cin, lstep);
    a64_kernel<<<HN, 256>>>();
    powers_kernel<<<HN, 128, SM_BYTES>>>();
    cbw_kernel<<<HN, 64>>>();
    econv_kernel<<<HN, 256>>>(u, Din, out);
    prop_kernel<<<HN, 256>>>(x0re, x0im);
    y1_kernel<<<HN, 256>>>(out);
}

// round 6
// speedup vs baseline: 1.6526x; 1.2112x over previous
#include <cuda_runtime.h>
#include <math.h>

#define HN 512
#define NS 64
#define LLEN 2048
#define CHUNKS 32

// ---------------- device scratch (no dynamic allocation) ----------------
__device__ float2 g_m[HN][NS];
__device__ float2 g_v[HN][NS];
__device__ float2 g_r[HN][NS];
__device__ float2 g_cct[HN][NS];
__device__ float  g_taps[HN][NS];
__device__ float2 g_T0[HN][NS * NS];     // A^32 (a64), then A^2048 (powers)
__device__ float2 g_AB64[HN][NS * NS];   // A^64 (powers step 0)
__device__ float2 g_K[HN][NS * NS];      // [p][n]
__device__ float2 g_Wt[HN][NS * NS];     // [n][tau]
__device__ float2 g_E[HN][CHUNKS][NS];
__device__ float  g_uT[HN][LLEN];        // u transposed
__device__ float  g_Y[HN][LLEN];         // per-head output row

// ---------------- complex helpers ----------------
__device__ __forceinline__ float2 cmul(float2 a, float2 b) {
    return make_float2(a.x * b.x - a.y * b.y, a.x * b.y + a.y * b.x);
}
__device__ __forceinline__ float2 csub(float2 a, float2 b) { return make_float2(a.x - b.x, a.y - b.y); }
__device__ __forceinline__ float2 conj2(float2 a) { return make_float2(a.x, -a.y); }
__device__ __forceinline__ float2 crcp(float2 a) {
    float inv = 1.0f / (a.x * a.x + a.y * a.y);
    return make_float2(a.x * inv, -a.y * inv);
}

__device__ __forceinline__ void fma2(unsigned long long& d, unsigned long long a, unsigned long long b) {
    asm("fma.rn.f32x2 %0, %1, %2, %0;" : "+l"(d) : "l"(a), "l"(b));
}
__device__ __forceinline__ float2 u2f(unsigned long long u) {
    float2 f;
    asm("mov.b64 {%0, %1}, %2;" : "=f"(f.x), "=f"(f.y) : "l"(u));
    return f;
}
__device__ __forceinline__ unsigned long long packdup(float a) {
    unsigned long long r;
    asm("mov.b64 %0, {%1, %1};" : "=l"(r) : "f"(a));
    return r;
}

__device__ __forceinline__ float2 blockReduce64(float2 val, float2* sbuf) {
    #pragma unroll
    for (int o = 16; o > 0; o >>= 1) {
        val.x += __shfl_xor_sync(0xffffffffu, val.x, o);
        val.y += __shfl_xor_sync(0xffffffffu, val.y, o);
    }
    int tid = threadIdx.x;
    if ((tid & 31) == 0) sbuf[tid >> 5] = val;
    __syncthreads();
    float2 res = make_float2(sbuf[0].x + sbuf[1].x, sbuf[0].y + sbuf[1].y);
    __syncthreads();
    return res;
}

__device__ __forceinline__ float2 warpReduce2(float dx, float dy) {
    #pragma unroll
    for (int o = 16; o > 0; o >>= 1) {
        dx += __shfl_xor_sync(0xffffffffu, dx, o);
        dy += __shfl_xor_sync(0xffffffffu, dy, o);
    }
    return make_float2(dx, dy);
}

// ---------------- transpose u -> uT ----------------
__global__ __launch_bounds__(256) void trans_in_kernel(const float* __restrict__ u) {
    __shared__ float tile[32][33];
    int tx = threadIdx.x, ty = threadIdx.y;
    int h0 = blockIdx.x * 32, t0 = blockIdx.y * 32;
    #pragma unroll
    for (int k = 0; k < 4; k++)
        tile[ty + 8 * k][tx] = u[(t0 + ty + 8 * k) * HN + h0 + tx];
    __syncthreads();
    #pragma unroll
    for (int k = 0; k < 4; k++)
        g_uT[h0 + ty + 8 * k][t0 + tx] = tile[tx][ty + 8 * k];
}

// ---------------- transpose g_Y -> out ----------------
__global__ __launch_bounds__(256) void trans_out_kernel(float* __restrict__ out) {
    __shared__ float tile[32][33];
    int tx = threadIdx.x, ty = threadIdx.y;
    int h0 = blockIdx.x * 32, t0 = blockIdx.y * 32;
    #pragma unroll
    for (int k = 0; k < 4; k++)
        tile[ty + 8 * k][tx] = g_Y[h0 + ty + 8 * k][t0 + tx];
    __syncthreads();
    #pragma unroll
    for (int k = 0; k < 4; k++)
        out[(t0 + ty + 8 * k) * HN + h0 + tx] = tile[tx][ty + 8 * k];
}

// ---------------- kernel 1: derive params + K chain ----------------
__global__ void derive_kernel(const float* __restrict__ Lre, const float* __restrict__ Lim,
                              const float* __restrict__ Pre, const float* __restrict__ Pim,
                              const float* __restrict__ Bre, const float* __restrict__ Bim,
                              const float* __restrict__ Cin, const float* __restrict__ lstep) {
    int h = blockIdx.x;
    int n = threadIdx.x;
    __shared__ float2 sred[2];
    __shared__ float2 sr[NS];
    __shared__ float2 sm_m[NS], sm_v[NS], sm_bb[NS];

    float dt = expf(lstep[h]);
    float tdt = 2.0f / dt;
    float lre = fminf(Lre[h * NS + n], -1e-4f);
    float lim = Lim[h * NS + n];

    float2 den = make_float2(tdt - lre, -lim);
    float2 d = crcp(den);
    float2 a0 = make_float2(tdt + lre, lim);
    float2 m = cmul(d, a0);
    float2 P = make_float2(Pre[h * NS + n], Pim[h * NS + n]);
    float p2 = P.x * P.x + P.y * P.y;

    float2 s = blockReduce64(make_float2(p2 * d.x, p2 * d.y), sred);
    float2 c = crcp(make_float2(1.0f + s.x, s.y));
    float2 v = cmul(d, P);
    float2 onem = make_float2(1.0f + m.x, m.y);
    float2 r = cmul(c, cmul(conj2(P), onem));

    float2 B = make_float2(Bre[h * NS + n], Bim[h * NS + n]);
    float2 t1 = cmul(cmul(conj2(P), B), d);
    float2 sB = blockReduce64(t1, sred);
    float2 cs = cmul(c, sB);
    float2 dB = cmul(d, B);
    float2 vcs = cmul(cs, v);
    float2 bb = make_float2(2.0f * (dB.x - vcs.x), 2.0f * (dB.y - vcs.y));

    float2 cct = make_float2(Cin[h * 2 * NS + 2 * n], -Cin[h * 2 * NS + 2 * n + 1]);

    g_m[h][n] = m; g_v[h][n] = v; g_r[h][n] = r; g_cct[h][n] = cct;

    sr[n] = r; sm_m[n] = m; sm_v[n] = v; sm_bb[n] = bb;
    __syncthreads();

    // K chain on warp 0: K_0 = Bb ; K_{p+1} = m*K_p - v*(r . K_p)
    if (n < 32) {
        float2 xa = sm_bb[n], xb = sm_bb[n + 32];
        float2 ra = sr[n], rb = sr[n + 32];
        float2 ma = sm_m[n], mb = sm_m[n + 32];
        float2 va = sm_v[n], vb = sm_v[n + 32];
        g_K[h][n] = xa; g_K[h][n + 32] = xb;
        for (int p = 1; p < NS; p++) {
            float2 d1 = cmul(ra, xa), d2 = cmul(rb, xb);
            float2 dot = warpReduce2(d1.x + d2.x, d1.y + d2.y);
            xa = csub(cmul(ma, xa), cmul(va, dot));
            xb = csub(cmul(mb, xb), cmul(vb, dot));
            g_K[h][p * NS + n] = xa;
            g_K[h][p * NS + n + 32] = xb;
        }
    }
}

// ---------------- kernel 2: A^32 via 31 structured steps ----------------
__global__ __launch_bounds__(256) void a64_kernel() {
    int h = blockIdx.x;
    int t = threadIdx.x;
    int j = t & 63;
    int q = t >> 6;
    __shared__ float2 sM[NS][NS + 1];
    __shared__ float2 srm[NS], smm[NS], svm[NS];
    __shared__ float2 spart[4][NS];

    if (t < NS) { srm[t] = g_r[h][t]; smm[t] = g_m[h][t]; svm[t] = g_v[h][t]; }
    __syncthreads();

    {
        float2 rj = srm[j];
        #pragma unroll
        for (int k = 0; k < 16; k++) {
            int n = q * 16 + k;
            float2 e = cmul(svm[n], rj);
            float2 val = make_float2(-e.x, -e.y);
            if (n == j) { val.x += smm[n].x; val.y += smm[n].y; }
            sM[n][j] = val;
        }
    }
    __syncthreads();

    for (int it = 0; it < 31; it++) {
        float2 Mreg[16];
        float2 acc = make_float2(0.0f, 0.0f);
        #pragma unroll
        for (int k = 0; k < 16; k++) {
            int n = q * 16 + k;
            Mreg[k] = sM[n][j];
            float2 rn = srm[n];
            acc.x = fmaf(rn.x, Mreg[k].x, fmaf(-rn.y, Mreg[k].y, acc.x));
            acc.y = fmaf(rn.x, Mreg[k].y, fmaf(rn.y, Mreg[k].x, acc.y));
        }
        spart[q][j] = acc;
        __syncthreads();
        float2 w;
        w.x = spart[0][j].x + spart[1][j].x + spart[2][j].x + spart[3][j].x;
        w.y = spart[0][j].y + spart[1][j].y + spart[2][j].y + spart[3][j].y;
        #pragma unroll
        for (int k = 0; k < 16; k++) {
            int n = q * 16 + k;
            float2 mn = smm[n], vn = svm[n];
            float2 nv;
            nv.x = mn.x * Mreg[k].x - mn.y * Mreg[k].y - (vn.x * w.x - vn.y * w.y);
            nv.y = mn.x * Mreg[k].y + mn.y * Mreg[k].x - (vn.x * w.y + vn.y * w.x);
            sM[n][j] = nv;
        }
        __syncthreads();
    }

    #pragma unroll
    for (int k = 0; k < 16; k++) {
        int n = q * 16 + k;
        g_T0[h][n * NS + j] = sM[n][j];
    }
}

// ---------------- kernel 3: 6 fused squarings A^32 -> A^2048, f32x2 ----------------
#define DROW 66
#define SM_BYTES (2 * 64 * DROW * 8 + 2 * 64 * DROW * 4)

__global__ __launch_bounds__(128, 2) void powers_kernel() {
    extern __shared__ char smraw[];
    float2* are_dup = (float2*)smraw;
    float2* aim_dup = are_dup + 64 * DROW;
    float*  brem    = (float*)(aim_dup + 64 * DROW);
    float*  bimm    = brem + 64 * DROW;

    int h = blockIdx.x;
    int t = threadIdx.x;

    for (int idx = t; idx < NS * NS; idx += 128) {
        int r = idx >> 6, c = idx & 63;
        float2 f = g_T0[h][idx];
        brem[r * DROW + c] = f.x;
        bimm[r * DROW + c] = f.y;
        are_dup[c * DROW + r] = make_float2(f.x, f.x);
        aim_dup[c * DROW + r] = make_float2(f.y, f.y);
    }
    __syncthreads();

    int r0 = (t >> 3) * 4;
    int ci = t & 7;

    for (int step = 0; step < 6; step++) {
        unsigned long long accRR[4][4] = {}, accII[4][4] = {}, accRI[4][4] = {}, accIR[4][4] = {};

        #pragma unroll 4
        for (int k = 0; k < NS; k++) {
            unsigned long long a_re[4], a_im[4];
            #pragma unroll
            for (int i = 0; i < 4; i++) {
                a_re[i] = *(const unsigned long long*)&are_dup[k * DROW + r0 + i];
                a_im[i] = *(const unsigned long long*)&aim_dup[k * DROW + r0 + i];
            }
            unsigned long long b_re[4], b_im[4];
            #pragma unroll
            for (int p = 0; p < 4; p++) {
                b_re[p] = *(const unsigned long long*)&brem[k * DROW + 2 * ci + 16 * p];
                b_im[p] = *(const unsigned long long*)&bimm[k * DROW + 2 * ci + 16 * p];
            }
            #pragma unroll
            for (int i = 0; i < 4; i++)
                #pragma unroll
                for (int p = 0; p < 4; p++) {
                    fma2(accRR[i][p], a_re[i], b_re[p]);
                    fma2(accII[i][p], a_im[i], b_im[p]);
                    fma2(accRI[i][p], a_re[i], b_im[p]);
                    fma2(accIR[i][p], a_im[i], b_re[p]);
                }
        }
        __syncthreads();

        bool saveA64 = (step == 0);      // result of step 0 squaring = A^64
        bool last = (step == 5);         // A^2048
        #pragma unroll
        for (int i = 0; i < 4; i++) {
            #pragma unroll
            for (int p = 0; p < 4; p++) {
                float2 rr = u2f(accRR[i][p]);
                float2 ii = u2f(accII[i][p]);
                float2 rim = u2f(accRI[i][p]);
                float2 ir = u2f(accIR[i][p]);
                float re0 = rr.x - ii.x, re1 = rr.y - ii.y;
                float im0 = rim.x + ir.x, im1 = rim.y + ir.y;
                int r = r0 + i;
                int j = 2 * ci + 16 * p;
                if (last) {
                    g_T0[h][r * NS + j] = make_float2(re0, im0);
                    g_T0[h][r * NS + j + 1] = make_float2(re1, im1);
                } else {
                    brem[r * DROW + j] = re0;     brem[r * DROW + j + 1] = re1;
                    bimm[r * DROW + j] = im0;     bimm[r * DROW + j + 1] = im1;
                    are_dup[j * DROW + r] = make_float2(re0, re0);
                    are_dup[(j + 1) * DROW + r] = make_float2(re1, re1);
                    aim_dup[j * DROW + r] = make_float2(im0, im0);
                    aim_dup[(j + 1) * DROW + r] = make_float2(im1, im1);
                    if (saveA64) {
                        g_AB64[h][r * NS + j] = make_float2(re0, im0);
                        g_AB64[h][r * NS + j + 1] = make_float2(re1, im1);
                    }
                }
            }
        }
        __syncthreads();
    }
}

// ---------------- kernel 4: Cb (Neumann k-split), Wt chain, taps ----------------
__global__ __launch_bounds__(256) void cbw_kernel() {
    int h = blockIdx.x;
    int t = threadIdx.x;
    int n = t & 63;
    int q = t >> 6;
    __shared__ float gre[NS][NS + 1];
    __shared__ float gim[NS][NS + 1];
    __shared__ float2 sw[NS];
    __shared__ float2 scct[NS];
    __shared__ float2 spart[4][NS];

    for (int idx = t; idx < NS * NS; idx += 256) {
        float2 f = g_T0[h][idx];
        gre[idx >> 6][idx & 63] = f.x;
        gim[idx >> 6][idx & 63] = f.y;
    }
    if (t < NS) {
        float2 c = g_cct[h][t];
        scct[t] = c;
        sw[t] = c;
    }
    __syncthreads();

    // w <- cct + w G, 10 iterations, k split 4-way
    for (int it = 0; it < 10; it++) {
        float2 acc0 = make_float2(0.f, 0.f), acc1 = make_float2(0.f, 0.f);
        int k0 = q * 16;
        #pragma unroll
        for (int kk = 0; kk < 16; kk += 2) {
            float2 w0 = sw[k0 + kk], w1 = sw[k0 + kk + 1];
            float2 gA = make_float2(gre[k0 + kk][n], gim[k0 + kk][n]);
            float2 gB = make_float2(gre[k0 + kk + 1][n], gim[k0 + kk + 1][n]);
            acc0.x = fmaf(w0.x, gA.x, fmaf(-w0.y, gA.y, acc0.x));
            acc0.y = fmaf(w0.x, gA.y, fmaf(w0.y, gA.x, acc0.y));
            acc1.x = fmaf(w1.x, gB.x, fmaf(-w1.y, gB.y, acc1.x));
            acc1.y = fmaf(w1.x, gB.y, fmaf(w1.y, gB.x, acc1.y));
        }
        spart[q][n] = make_float2(acc0.x + acc1.x, acc0.y + acc1.y);
        __syncthreads();
        if (q == 0) {
            float2 w;
            w.x = scct[n].x + spart[0][n].x + spart[1][n].x + spart[2][n].x + spart[3][n].x;
            w.y = scct[n].y + spart[0][n].y + spart[1][n].y + spart[2][n].y + spart[3][n].y;
            sw[n] = w;
        }
        __syncthreads();
    }

    if (t < 32) {
        // Wt chain on warp 0 (2 states/lane)
        float2 wa = sw[t], wb = sw[t + 32];
        float2 ma = g_m[h][t], mb = g_m[h][t + 32];
        float2 va = g_v[h][t], vb = g_v[h][t + 32];
        float2 ra = g_r[h][t], rb = g_r[h][t + 32];
        for (int tau = 0; tau < NS; tau++) {
            float2 d1 = cmul(wa, va), d2 = cmul(wb, vb);
            float2 dot = warpReduce2(d1.x + d2.x, d1.y + d2.y);
            wa = csub(cmul(ma, wa), cmul(dot, ra));
            wb = csub(cmul(mb, wb), cmul(dot, rb));
            g_Wt[h][t * NS + tau] = wa;
            g_Wt[h][(t + 32) * NS + tau] = wb;
        }
    } else if (t >= 64 && t < 128) {
        // taps on warps 2-3: p = t - 64
        int p = t - 64;
        float acc = 0.0f;
        #pragma unroll 4
        for (int i = 0; i < NS; i++) {
            float2 kp = g_K[h][p * NS + i];
            float2 ci = sw[i];
            acc = fmaf(ci.x, kp.x, fmaf(-ci.y, kp.y, acc));
        }
        g_taps[h][p] = acc;
    }
}

// ---------------- kernel 5: chunk-local ends E + causal conv -> g_Y ----------------
__global__ __launch_bounds__(256) void econv_kernel(const float* __restrict__ Din) {
    int h = blockIdx.x;
    int t = threadIdx.x;
    __shared__ float su[LLEN];
    __shared__ float2 kc[NS][NS];
    __shared__ float stp[2 * NS];

    for (int i = t; i < LLEN; i += 256) su[i] = g_uT[h][i];
    for (int idx = t; idx < NS * NS; idx += 256) kc[idx >> 6][idx & 63] = g_K[h][idx];
    if (t < NS) { stp[t] = 0.0f; stp[NS + t] = g_taps[h][t]; }
    __syncthreads();

    float Dh = Din[h];
    int n = t & 63;
    int jb = t >> 6;
    for (int jj = 0; jj < 8; jj++) {
        int j = jb * 8 + jj;
        const float* uj = &su[j * 64];
        unsigned long long acc2a = 0ull, acc2b = 0ull, acc2c = 0ull, acc2d = 0ull;
        float yc0 = 0.0f, yc1 = 0.0f, yc2 = 0.0f, yc3 = 0.0f;
        #pragma unroll 8
        for (int s = 0; s < 64; s += 4) {
            float us0 = uj[s], us1 = uj[s + 1], us2 = uj[s + 2], us3 = uj[s + 3];
            fma2(acc2a, *(const unsigned long long*)&kc[63 - s][n], packdup(us0));
            fma2(acc2b, *(const unsigned long long*)&kc[62 - s][n], packdup(us1));
            fma2(acc2c, *(const unsigned long long*)&kc[61 - s][n], packdup(us2));
            fma2(acc2d, *(const unsigned long long*)&kc[60 - s][n], packdup(us3));
            yc0 = fmaf(stp[NS + n - s], us0, yc0);
            yc1 = fmaf(stp[NS + n - s - 1], us1, yc1);
            yc2 = fmaf(stp[NS + n - s - 2], us2, yc2);
            yc3 = fmaf(stp[NS + n - s - 3], us3, yc3);
        }
        float2 ea = u2f(acc2a), eb = u2f(acc2b), ec = u2f(acc2c), ed = u2f(acc2d);
        g_E[h][j][n] = make_float2(ea.x + eb.x + ec.x + ed.x, ea.y + eb.y + ec.y + ed.y);
        int tg = j * 64 + n;
        g_Y[h][tg] = (yc0 + yc1) + (yc2 + yc3) + Dh * su[tg];
    }
}

// ---------------- kernel 6: fused carry propagation + Y1 -> g_Y ----------------
#define PY_SMEM (2 * 64 * 65 * 4 + 64 * 64 * 8 + 32 * 64 * 8 + 64 * 8 + 4 * 64 * 8)

__global__ __launch_bounds__(256, 2) void propy1_kernel(const float* __restrict__ x0re,
                                                        const float* __restrict__ x0im) {
    extern __shared__ char sm[];
    float*  ar    = (float*)sm;                     // [64][65]
    float*  ai    = ar + 64 * 65;                   // [64][65]
    float2* wc    = (float2*)(ai + 64 * 65);        // [64][64] (n, tau)
    float2* xs2   = wc + 64 * 64;                   // [32][64] (x, -y)
    float2* sx    = xs2 + 32 * 64;                  // [64]
    float2* spart = sx + 64;                        // [4][64]

    int h = blockIdx.x;
    int t = threadIdx.x;
    int n = t & 63;
    int q = t >> 6;

    for (int idx = t; idx < NS * NS; idx += 256) {
        float2 f = g_AB64[h][idx];
        ar[(idx >> 6) * 65 + (idx & 63)] = f.x;
        ai[(idx >> 6) * 65 + (idx & 63)] = f.y;
    }
    for (int idx = t; idx < NS * NS; idx += 256) wc[idx] = g_Wt[h][idx];

    float2 x;
    if (q == 0) {
        x = make_float2(x0re[n * HN + h], x0im[n * HN + h]);
        sx[n] = x;
    }
    __syncthreads();

    int k0 = q * 16;
    for (int j = 0; j < CHUNKS; j++) {
        if (q == 0) xs2[j * 64 + n] = make_float2(x.x, -x.y);
        float2 acc = make_float2(0.0f, 0.0f);
        #pragma unroll
        for (int kk = 0; kk < 16; kk++) {
            int k = k0 + kk;
            float arr = ar[n * 65 + k], aii = ai[n * 65 + k];
            float2 xk = sx[k];
            acc.x = fmaf(arr, xk.x, fmaf(-aii, xk.y, acc.x));
            acc.y = fmaf(arr, xk.y, fmaf(aii, xk.x, acc.y));
        }
        spart[q * 64 + n] = acc;
        __syncthreads();
        if (q == 0) {
            float2 e = g_E[h][j][n];
            x.x = e.x + spart[n].x + spart[64 + n].x + spart[128 + n].x + spart[192 + n].x;
            x.y = e.y + spart[n].y + spart[64 + n].y + spart[128 + n].y + spart[192 + n].y;
            sx[n] = x;
        }
        __syncthreads();
    }

    // Y1: g_Y[h][j*64+tau] += Re( sum_n Wt[n][tau] * x_j[n] )
    int tau = n;
    for (int jj = 0; jj < 8; jj++) {
        int j = q * 8 + jj;
        unsigned long long acc2 = 0ull, acc2b = 0ull;
        #pragma unroll 8
        for (int nn = 0; nn < NS; nn += 2) {
            fma2(acc2,  *(const unsigned long long*)&wc[nn * 64 + tau],       *(const unsigned long long*)&xs2[j * 64 + nn]);
            fma2(acc2b, *(const unsigned long long*)&wc[(nn + 1) * 64 + tau], *(const unsigned long long*)&xs2[j * 64 + nn + 1]);
        }
        float2 f = u2f(acc2);
        float2 fb = u2f(acc2b);
        g_Y[h][j * 64 + tau] += (f.x + f.y) + (fb.x + fb.y);
    }
}

// ---------------- launch ----------------
extern "C" void kernel_launch(void* const* d_in, const int* in_sizes, int n_in,
                              void* d_out, int out_size) {
    const float* u     = (const float*)d_in[0];
    const float* x0re  = (const float*)d_in[1];
    const float* x0im  = (const float*)d_in[2];
    const float* Lre   = (const float*)d_in[3];
    const float* Lim   = (const float*)d_in[4];
    const float* Pre   = (const float*)d_in[5];
    const float* Pim   = (const float*)d_in[6];
    const float* Bre   = (const float*)d_in[7];
    const float* Bim   = (const float*)d_in[8];
    const float* Cin   = (const float*)d_in[9];
    const float* Din   = (const float*)d_in[10];
    const float* lstep = (const float*)d_in[11];
    float* out = (float*)d_out;

    cudaFuncSetAttribute(powers_kernel, cudaFuncAttributeMaxDynamicSharedMemorySize, SM_BYTES);
    cudaFuncSetAttribute(propy1_kernel, cudaFuncAttributeMaxDynamicSharedMemorySize, PY_SMEM);

    dim3 tb(32, 8);
    dim3 tg(HN / 32, LLEN / 32);
    trans_in_kernel<<<tg, tb>>>(u);
    derive_kernel<<<HN, 64>>>(Lre, Lim, Pre, Pim, Bre, Bim, Cin, lstep);
    a64_kernel<<<HN, 256>>>();
    powers_kernel<<<HN, 128, SM_BYTES>>>();
    cbw_kernel<<<HN, 256>>>();
    econv_kernel<<<HN, 256>>>(Din);
    propy1_kernel<<<HN, 256, PY_SMEM>>>(x0re, x0im);
    trans_out_kernel<<<tg, tb>>>(out);
}

// round 7
// speedup vs baseline: 1.7519x; 1.0600x over previous
#include <cuda_runtime.h>
#include <math.h>

#define HN 512
#define NS 64
#define LLEN 2048
#define CHUNKS 32

// ---------------- device scratch (no dynamic allocation) ----------------
__device__ float2 g_m[HN][NS];
__device__ float2 g_v[HN][NS];
__device__ float2 g_r[HN][NS];
__device__ float2 g_cct[HN][NS];
__device__ float  g_taps[HN][NS];
__device__ float2 g_T0[HN][NS * NS];     // A^32 (a64), then A^2048 (powers)
__device__ float2 g_AB64[HN][NS * NS];   // A^64 (powers step 0)
__device__ float2 g_K[HN][NS * NS];      // [p][n]
__device__ float2 g_Wt[HN][NS * NS];     // [n][tau]
__device__ float2 g_E[HN][CHUNKS][NS];
__device__ float  g_uT[HN][LLEN];        // u transposed
__device__ float  g_Y[HN][LLEN];         // per-head output row

// ---------------- complex helpers ----------------
__device__ __forceinline__ float2 cmul(float2 a, float2 b) {
    return make_float2(a.x * b.x - a.y * b.y, a.x * b.y + a.y * b.x);
}
__device__ __forceinline__ float2 csub(float2 a, float2 b) { return make_float2(a.x - b.x, a.y - b.y); }
__device__ __forceinline__ float2 conj2(float2 a) { return make_float2(a.x, -a.y); }
__device__ __forceinline__ float2 crcp(float2 a) {
    float inv = 1.0f / (a.x * a.x + a.y * a.y);
    return make_float2(a.x * inv, -a.y * inv);
}

__device__ __forceinline__ void fma2(unsigned long long& d, unsigned long long a, unsigned long long b) {
    asm("fma.rn.f32x2 %0, %1, %2, %0;" : "+l"(d) : "l"(a), "l"(b));
}
__device__ __forceinline__ float2 u2f(unsigned long long u) {
    float2 f;
    asm("mov.b64 {%0, %1}, %2;" : "=f"(f.x), "=f"(f.y) : "l"(u));
    return f;
}
__device__ __forceinline__ unsigned long long packdup(float a) {
    unsigned long long r;
    asm("mov.b64 %0, {%1, %1};" : "=l"(r) : "f"(a));
    return r;
}

__device__ __forceinline__ float2 blockReduce64(float2 val, float2* sbuf) {
    #pragma unroll
    for (int o = 16; o > 0; o >>= 1) {
        val.x += __shfl_xor_sync(0xffffffffu, val.x, o);
        val.y += __shfl_xor_sync(0xffffffffu, val.y, o);
    }
    int tid = threadIdx.x;
    if ((tid & 31) == 0) sbuf[tid >> 5] = val;
    __syncthreads();
    float2 res = make_float2(sbuf[0].x + sbuf[1].x, sbuf[0].y + sbuf[1].y);
    __syncthreads();
    return res;
}

__device__ __forceinline__ float2 warpReduce2(float dx, float dy) {
    #pragma unroll
    for (int o = 16; o > 0; o >>= 1) {
        dx += __shfl_xor_sync(0xffffffffu, dx, o);
        dy += __shfl_xor_sync(0xffffffffu, dy, o);
    }
    return make_float2(dx, dy);
}

// ---------------- transpose u -> uT ----------------
__global__ __launch_bounds__(256) void trans_in_kernel(const float* __restrict__ u) {
    __shared__ float tile[32][33];
    int tx = threadIdx.x, ty = threadIdx.y;
    int h0 = blockIdx.x * 32, t0 = blockIdx.y * 32;
    #pragma unroll
    for (int k = 0; k < 4; k++)
        tile[ty + 8 * k][tx] = u[(t0 + ty + 8 * k) * HN + h0 + tx];
    __syncthreads();
    #pragma unroll
    for (int k = 0; k < 4; k++)
        g_uT[h0 + ty + 8 * k][t0 + tx] = tile[tx][ty + 8 * k];
}

// ---------------- transpose g_Y -> out ----------------
__global__ __launch_bounds__(256) void trans_out_kernel(float* __restrict__ out) {
    __shared__ float tile[32][33];
    int tx = threadIdx.x, ty = threadIdx.y;
    int h0 = blockIdx.x * 32, t0 = blockIdx.y * 32;
    #pragma unroll
    for (int k = 0; k < 4; k++)
        tile[ty + 8 * k][tx] = g_Y[h0 + ty + 8 * k][t0 + tx];
    __syncthreads();
    #pragma unroll
    for (int k = 0; k < 4; k++)
        out[(t0 + ty + 8 * k) * HN + h0 + tx] = tile[tx][ty + 8 * k];
}

// ---------------- kernel 1: derive params + K chain ----------------
__global__ void derive_kernel(const float* __restrict__ Lre, const float* __restrict__ Lim,
                              const float* __restrict__ Pre, const float* __restrict__ Pim,
                              const float* __restrict__ Bre, const float* __restrict__ Bim,
                              const float* __restrict__ Cin, const float* __restrict__ lstep) {
    int h = blockIdx.x;
    int n = threadIdx.x;
    __shared__ float2 sred[2];
    __shared__ float2 sr[NS];
    __shared__ float2 sm_m[NS], sm_v[NS], sm_bb[NS];

    float dt = expf(lstep[h]);
    float tdt = 2.0f / dt;
    float lre = fminf(Lre[h * NS + n], -1e-4f);
    float lim = Lim[h * NS + n];

    float2 den = make_float2(tdt - lre, -lim);
    float2 d = crcp(den);
    float2 a0 = make_float2(tdt + lre, lim);
    float2 m = cmul(d, a0);
    float2 P = make_float2(Pre[h * NS + n], Pim[h * NS + n]);
    float p2 = P.x * P.x + P.y * P.y;

    float2 s = blockReduce64(make_float2(p2 * d.x, p2 * d.y), sred);
    float2 c = crcp(make_float2(1.0f + s.x, s.y));
    float2 v = cmul(d, P);
    float2 onem = make_float2(1.0f + m.x, m.y);
    float2 r = cmul(c, cmul(conj2(P), onem));

    float2 B = make_float2(Bre[h * NS + n], Bim[h * NS + n]);
    float2 t1 = cmul(cmul(conj2(P), B), d);
    float2 sB = blockReduce64(t1, sred);
    float2 cs = cmul(c, sB);
    float2 dB = cmul(d, B);
    float2 vcs = cmul(cs, v);
    float2 bb = make_float2(2.0f * (dB.x - vcs.x), 2.0f * (dB.y - vcs.y));

    float2 cct = make_float2(Cin[h * 2 * NS + 2 * n], -Cin[h * 2 * NS + 2 * n + 1]);

    g_m[h][n] = m; g_v[h][n] = v; g_r[h][n] = r; g_cct[h][n] = cct;

    sr[n] = r; sm_m[n] = m; sm_v[n] = v; sm_bb[n] = bb;
    __syncthreads();

    // K chain on warp 0: K_0 = Bb ; K_{p+1} = m*K_p - v*(r . K_p)
    if (n < 32) {
        float2 xa = sm_bb[n], xb = sm_bb[n + 32];
        float2 ra = sr[n], rb = sr[n + 32];
        float2 ma = sm_m[n], mb = sm_m[n + 32];
        float2 va = sm_v[n], vb = sm_v[n + 32];
        g_K[h][n] = xa; g_K[h][n + 32] = xb;
        for (int p = 1; p < NS; p++) {
            float2 d1 = cmul(ra, xa), d2 = cmul(rb, xb);
            float2 dot = warpReduce2(d1.x + d2.x, d1.y + d2.y);
            xa = csub(cmul(ma, xa), cmul(va, dot));
            xb = csub(cmul(mb, xb), cmul(vb, dot));
            g_K[h][p * NS + n] = xa;
            g_K[h][p * NS + n + 32] = xb;
        }
    }
}

// ---------------- kernel 2: A^32 via 31 structured steps ----------------
__global__ __launch_bounds__(256) void a64_kernel() {
    int h = blockIdx.x;
    int t = threadIdx.x;
    int j = t & 63;
    int q = t >> 6;
    __shared__ float2 sM[NS][NS + 1];
    __shared__ float2 srm[NS], smm[NS], svm[NS];
    __shared__ float2 spart[4][NS];

    if (t < NS) { srm[t] = g_r[h][t]; smm[t] = g_m[h][t]; svm[t] = g_v[h][t]; }
    __syncthreads();

    {
        float2 rj = srm[j];
        #pragma unroll
        for (int k = 0; k < 16; k++) {
            int n = q * 16 + k;
            float2 e = cmul(svm[n], rj);
            float2 val = make_float2(-e.x, -e.y);
            if (n == j) { val.x += smm[n].x; val.y += smm[n].y; }
            sM[n][j] = val;
        }
    }
    __syncthreads();

    for (int it = 0; it < 31; it++) {
        float2 Mreg[16];
        float2 acc = make_float2(0.0f, 0.0f);
        #pragma unroll
        for (int k = 0; k < 16; k++) {
            int n = q * 16 + k;
            Mreg[k] = sM[n][j];
            float2 rn = srm[n];
            acc.x = fmaf(rn.x, Mreg[k].x, fmaf(-rn.y, Mreg[k].y, acc.x));
            acc.y = fmaf(rn.x, Mreg[k].y, fmaf(rn.y, Mreg[k].x, acc.y));
        }
        spart[q][j] = acc;
        __syncthreads();
        float2 w;
        w.x = spart[0][j].x + spart[1][j].x + spart[2][j].x + spart[3][j].x;
        w.y = spart[0][j].y + spart[1][j].y + spart[2][j].y + spart[3][j].y;
        #pragma unroll
        for (int k = 0; k < 16; k++) {
            int n = q * 16 + k;
            float2 mn = smm[n], vn = svm[n];
            float2 nv;
            nv.x = mn.x * Mreg[k].x - mn.y * Mreg[k].y - (vn.x * w.x - vn.y * w.y);
            nv.y = mn.x * Mreg[k].y + mn.y * Mreg[k].x - (vn.x * w.y + vn.y * w.x);
            sM[n][j] = nv;
        }
        __syncthreads();
    }

    #pragma unroll
    for (int k = 0; k < 16; k++) {
        int n = q * 16 + k;
        g_T0[h][n * NS + j] = sM[n][j];
    }
}

// ---------------- kernel 3: 6 fused squarings A^32 -> A^2048, f32x2, slim smem ----------------
#define DROW 66
#define SM_BYTES (2 * 64 * DROW * 4)

__global__ __launch_bounds__(128, 3) void powers_kernel() {
    extern __shared__ char smraw[];
    float* brem = (float*)smraw;            // [64][DROW]: re of A[r][c]
    float* bimm = brem + 64 * DROW;         // [64][DROW]: im of A[r][c]

    int h = blockIdx.x;
    int t = threadIdx.x;

    for (int idx = t; idx < NS * NS; idx += 128) {
        int r = idx >> 6, c = idx & 63;
        float2 f = g_T0[h][idx];
        brem[r * DROW + c] = f.x;
        bimm[r * DROW + c] = f.y;
    }
    __syncthreads();

    int r0 = (t >> 3) * 4;      // 16 row-groups of 4
    int ci = t & 7;             // 8 col-groups; pairs at 2ci + 16p, p=0..3

    for (int step = 0; step < 6; step++) {
        unsigned long long accRR[4][4] = {}, accII[4][4] = {}, accRI[4][4] = {}, accIR[4][4] = {};

        #pragma unroll 4
        for (int k = 0; k < NS; k++) {
            unsigned long long a_re[4], a_im[4];
            #pragma unroll
            for (int i = 0; i < 4; i++) {
                a_re[i] = packdup(brem[(r0 + i) * DROW + k]);
                a_im[i] = packdup(bimm[(r0 + i) * DROW + k]);
            }
            unsigned long long b_re[4], b_im[4];
            #pragma unroll
            for (int p = 0; p < 4; p++) {
                b_re[p] = *(const unsigned long long*)&brem[k * DROW + 2 * ci + 16 * p];
                b_im[p] = *(const unsigned long long*)&bimm[k * DROW + 2 * ci + 16 * p];
            }
            #pragma unroll
            for (int i = 0; i < 4; i++)
                #pragma unroll
                for (int p = 0; p < 4; p++) {
                    fma2(accRR[i][p], a_re[i], b_re[p]);
                    fma2(accII[i][p], a_im[i], b_im[p]);
                    fma2(accRI[i][p], a_re[i], b_im[p]);
                    fma2(accIR[i][p], a_im[i], b_re[p]);
                }
        }
        __syncthreads();

        bool saveA64 = (step == 0);
        bool last = (step == 5);
        #pragma unroll
        for (int i = 0; i < 4; i++) {
            #pragma unroll
            for (int p = 0; p < 4; p++) {
                float2 rr = u2f(accRR[i][p]);
                float2 ii = u2f(accII[i][p]);
                float2 rim = u2f(accRI[i][p]);
                float2 ir = u2f(accIR[i][p]);
                float re0 = rr.x - ii.x, re1 = rr.y - ii.y;
                float im0 = rim.x + ir.x, im1 = rim.y + ir.y;
                int r = r0 + i;
                int j = 2 * ci + 16 * p;
                if (last) {
                    g_T0[h][r * NS + j] = make_float2(re0, im0);
                    g_T0[h][r * NS + j + 1] = make_float2(re1, im1);
                } else {
                    brem[r * DROW + j] = re0;     brem[r * DROW + j + 1] = re1;
                    bimm[r * DROW + j] = im0;     bimm[r * DROW + j + 1] = im1;
                    if (saveA64) {
                        g_AB64[h][r * NS + j] = make_float2(re0, im0);
                        g_AB64[h][r * NS + j + 1] = make_float2(re1, im1);
                    }
                }
            }
        }
        __syncthreads();
    }
}

// ---------------- kernel 4: Cb (Neumann k-split), Wt chain, taps ----------------
__global__ __launch_bounds__(256) void cbw_kernel() {
    int h = blockIdx.x;
    int t = threadIdx.x;
    int n = t & 63;
    int q = t >> 6;
    __shared__ float gre[NS][NS + 1];
    __shared__ float gim[NS][NS + 1];
    __shared__ float2 sw[NS];
    __shared__ float2 scct[NS];
    __shared__ float2 spart[4][NS];

    for (int idx = t; idx < NS * NS; idx += 256) {
        float2 f = g_T0[h][idx];
        gre[idx >> 6][idx & 63] = f.x;
        gim[idx >> 6][idx & 63] = f.y;
    }
    if (t < NS) {
        float2 c = g_cct[h][t];
        scct[t] = c;
        sw[t] = c;
    }
    __syncthreads();

    for (int it = 0; it < 10; it++) {
        float2 acc0 = make_float2(0.f, 0.f), acc1 = make_float2(0.f, 0.f);
        int k0 = q * 16;
        #pragma unroll
        for (int kk = 0; kk < 16; kk += 2) {
            float2 w0 = sw[k0 + kk], w1 = sw[k0 + kk + 1];
            float2 gA = make_float2(gre[k0 + kk][n], gim[k0 + kk][n]);
            float2 gB = make_float2(gre[k0 + kk + 1][n], gim[k0 + kk + 1][n]);
            acc0.x = fmaf(w0.x, gA.x, fmaf(-w0.y, gA.y, acc0.x));
            acc0.y = fmaf(w0.x, gA.y, fmaf(w0.y, gA.x, acc0.y));
            acc1.x = fmaf(w1.x, gB.x, fmaf(-w1.y, gB.y, acc1.x));
            acc1.y = fmaf(w1.x, gB.y, fmaf(w1.y, gB.x, acc1.y));
        }
        spart[q][n] = make_float2(acc0.x + acc1.x, acc0.y + acc1.y);
        __syncthreads();
        if (q == 0) {
            float2 w;
            w.x = scct[n].x + spart[0][n].x + spart[1][n].x + spart[2][n].x + spart[3][n].x;
            w.y = scct[n].y + spart[0][n].y + spart[1][n].y + spart[2][n].y + spart[3][n].y;
            sw[n] = w;
        }
        __syncthreads();
    }

    if (t < 32) {
        float2 wa = sw[t], wb = sw[t + 32];
        float2 ma = g_m[h][t], mb = g_m[h][t + 32];
        float2 va = g_v[h][t], vb = g_v[h][t + 32];
        float2 ra = g_r[h][t], rb = g_r[h][t + 32];
        for (int tau = 0; tau < NS; tau++) {
            float2 d1 = cmul(wa, va), d2 = cmul(wb, vb);
            float2 dot = warpReduce2(d1.x + d2.x, d1.y + d2.y);
            wa = csub(cmul(ma, wa), cmul(dot, ra));
            wb = csub(cmul(mb, wb), cmul(dot, rb));
            g_Wt[h][t * NS + tau] = wa;
            g_Wt[h][(t + 32) * NS + tau] = wb;
        }
    } else if (t >= 64 && t < 128) {
        int p = t - 64;
        float acc = 0.0f;
        #pragma unroll 4
        for (int i = 0; i < NS; i++) {
            float2 kp = g_K[h][p * NS + i];
            float2 ci = sw[i];
            acc = fmaf(ci.x, kp.x, fmaf(-ci.y, kp.y, acc));
        }
        g_taps[h][p] = acc;
    }
}

// ---------------- kernel 5: chunk-local ends E + causal conv -> g_Y ----------------
__global__ __launch_bounds__(256) void econv_kernel(const float* __restrict__ Din) {
    int h = blockIdx.x;
    int t = threadIdx.x;
    __shared__ float su[LLEN];
    __shared__ float2 kc[NS][NS];
    __shared__ float stp[2 * NS];

    for (int i = t; i < LLEN; i += 256) su[i] = g_uT[h][i];
    for (int idx = t; idx < NS * NS; idx += 256) kc[idx >> 6][idx & 63] = g_K[h][idx];
    if (t < NS) { stp[t] = 0.0f; stp[NS + t] = g_taps[h][t]; }
    __syncthreads();

    float Dh = Din[h];
    int n = t & 63;
    int jb = t >> 6;
    for (int jj = 0; jj < 8; jj++) {
        int j = jb * 8 + jj;
        const float* uj = &su[j * 64];
        unsigned long long acc2a = 0ull, acc2b = 0ull, acc2c = 0ull, acc2d = 0ull;
        float yc0 = 0.0f, yc1 = 0.0f, yc2 = 0.0f, yc3 = 0.0f;
        #pragma unroll 8
        for (int s = 0; s < 64; s += 4) {
            float us0 = uj[s], us1 = uj[s + 1], us2 = uj[s + 2], us3 = uj[s + 3];
            fma2(acc2a, *(const unsigned long long*)&kc[63 - s][n], packdup(us0));
            fma2(acc2b, *(const unsigned long long*)&kc[62 - s][n], packdup(us1));
            fma2(acc2c, *(const unsigned long long*)&kc[61 - s][n], packdup(us2));
            fma2(acc2d, *(const unsigned long long*)&kc[60 - s][n], packdup(us3));
            yc0 = fmaf(stp[NS + n - s], us0, yc0);
            yc1 = fmaf(stp[NS + n - s - 1], us1, yc1);
            yc2 = fmaf(stp[NS + n - s - 2], us2, yc2);
            yc3 = fmaf(stp[NS + n - s - 3], us3, yc3);
        }
        float2 ea = u2f(acc2a), eb = u2f(acc2b), ec = u2f(acc2c), ed = u2f(acc2d);
        g_E[h][j][n] = make_float2(ea.x + eb.x + ec.x + ed.x, ea.y + eb.y + ec.y + ed.y);
        int tg = j * 64 + n;
        g_Y[h][tg] = (yc0 + yc1) + (yc2 + yc3) + Dh * su[tg];
    }
}

// ---------------- kernel 6: fused carry propagation + Y1 -> g_Y ----------------
// smem: ac[64][65] float2 (packed A^64) + wc[64][64] float2 + xs2[32][64] float2 + sx + spart
#define PY_SMEM (64 * 65 * 8 + 64 * 64 * 8 + 32 * 64 * 8 + 64 * 8 + 4 * 64 * 8)

__global__ __launch_bounds__(256, 2) void propy1_kernel(const float* __restrict__ x0re,
                                                        const float* __restrict__ x0im) {
    extern __shared__ char sm[];
    float2* ac    = (float2*)sm;                    // [64][65] (re,im)
    float2* wc    = ac + 64 * 65;                   // [64][64] (n, tau)
    float2* xs2   = wc + 64 * 64;                   // [32][64] (x, -y)
    float2* sx    = xs2 + 32 * 64;                  // [64]
    float2* spart = sx + 64;                        // [4][64]

    int h = blockIdx.x;
    int t = threadIdx.x;
    int n = t & 63;
    int q = t >> 6;

    for (int idx = t; idx < NS * NS; idx += 256)
        ac[(idx >> 6) * 65 + (idx & 63)] = g_AB64[h][idx];
    for (int idx = t; idx < NS * NS; idx += 256) wc[idx] = g_Wt[h][idx];

    float2 x;
    if (q == 0) {
        x = make_float2(x0re[n * HN + h], x0im[n * HN + h]);
        sx[n] = x;
    }
    __syncthreads();

    int k0 = q * 16;
    for (int j = 0; j < CHUNKS; j++) {
        if (q == 0) xs2[j * 64 + n] = make_float2(x.x, -x.y);
        float2 acc = make_float2(0.0f, 0.0f);
        #pragma unroll
        for (int kk = 0; kk < 16; kk++) {
            int k = k0 + kk;
            float2 a = ac[n * 65 + k];
            float2 xk = sx[k];
            acc.x = fmaf(a.x, xk.x, fmaf(-a.y, xk.y, acc.x));
            acc.y = fmaf(a.x, xk.y, fmaf(a.y, xk.x, acc.y));
        }
        spart[q * 64 + n] = acc;
        __syncthreads();
        if (q == 0) {
            float2 e = g_E[h][j][n];
            x.x = e.x + spart[n].x + spart[64 + n].x + spart[128 + n].x + spart[192 + n].x;
            x.y = e.y + spart[n].y + spart[64 + n].y + spart[128 + n].y + spart[192 + n].y;
            sx[n] = x;
        }
        __syncthreads();
    }

    // Y1: g_Y[h][j*64+tau] += Re( sum_n Wt[n][tau] * x_j[n] )
    int tau = n;
    for (int jj = 0; jj < 8; jj++) {
        int j = q * 8 + jj;
        unsigned long long acc2 = 0ull, acc2b = 0ull;
        #pragma unroll 8
        for (int nn = 0; nn < NS; nn += 2) {
            fma2(acc2,  *(const unsigned long long*)&wc[nn * 64 + tau],       *(const unsigned long long*)&xs2[j * 64 + nn]);
            fma2(acc2b, *(const unsigned long long*)&wc[(nn + 1) * 64 + tau], *(const unsigned long long*)&xs2[j * 64 + nn + 1]);
        }
        float2 f = u2f(acc2);
        float2 fb = u2f(acc2b);
        g_Y[h][j * 64 + tau] += (f.x + f.y) + (fb.x + fb.y);
    }
}

// ---------------- launch ----------------
extern "C" void kernel_launch(void* const* d_in, const int* in_sizes, int n_in,
                              void* d_out, int out_size) {
    const float* u     = (const float*)d_in[0];
    const float* x0re  = (const float*)d_in[1];
    const float* x0im  = (const float*)d_in[2];
    const float* Lre   = (const float*)d_in[3];
    const float* Lim   = (const float*)d_in[4];
    const float* Pre   = (const float*)d_in[5];
    const float* Pim   = (const float*)d_in[6];
    const float* Bre   = (const float*)d_in[7];
    const float* Bim   = (const float*)d_in[8];
    const float* Cin   = (const float*)d_in[9];
    const float* Din   = (const float*)d_in[10];
    const float* lstep = (const float*)d_in[11];
    float* out = (float*)d_out;

    cudaFuncSetAttribute(propy1_kernel, cudaFuncAttributeMaxDynamicSharedMemorySize, PY_SMEM);

    dim3 tb(32, 8);
    dim3 tg(HN / 32, LLEN / 32);
    trans_in_kernel<<<tg, tb>>>(u);
    derive_kernel<<<HN, 64>>>(Lre, Lim, Pre, Pim, Bre, Bim, Cin, lstep);
    a64_kernel<<<HN, 256>>>();
    powers_kernel<<<HN, 128, SM_BYTES>>>();
    cbw_kernel<<<HN, 256>>>();
    econv_kernel<<<HN, 256>>>(Din);
    propy1_kernel<<<HN, 256, PY_SMEM>>>(x0re, x0im);
    trans_out_kernel<<<tg, tb>>>(out);
}